// round 7
// baseline (speedup 1.0000x reference)
#include <cuda_runtime.h>
#include <math.h>

#define RUNS 512
#define WAYS 5
#define SHOT 5
#define NSUP 25
#define NQ   75
#define N100 100
#define N105 105
#define DIM  640
#define LAMv 10.0f
#define EPSV 0.001f
#define TP   113
#define MAXIT 1000
#define SNAPMAX 128

__device__ float g_feat[(size_t)RUNS*N105*DIM];
__device__ float g_proto[(size_t)RUNS*WAYS*DIM];
__device__ float g_M[(size_t)RUNS*NQ*WAYS];
__device__ float g_Z[(size_t)RUNS*N105*WAYS];
__device__ float g_E100[(size_t)RUNS*N100*N100];
__device__ float g_snap[(size_t)RUNS*SNAPMAX*WAYS*128];
__device__ int   g_nsnap[RUNS];
__device__ int   g_T[8];
__device__ int   g_bad[6*1024];

__device__ __forceinline__ float wredSum(float v){
    #pragma unroll
    for (int o=16;o;o>>=1) v += __shfl_xor_sync(0xffffffffu, v, o);
    return v;
}

// ---- K0: copy features, initial prototypes, reset T/bad ----
__global__ void __launch_bounds__(256) k_init(const float* __restrict__ xs,
                                              const float* __restrict__ xq){
    int b = blockIdx.x, tid = threadIdx.x;
    if (b==0){
        if (tid<8) g_T[tid]=0;
        for (int t=tid; t<6*1024; t+=256) g_bad[t]=0;
    }
    float* fb = g_feat + (size_t)b*N105*DIM;
    const float* s0 = xs + (size_t)b*NSUP*DIM;
    const float* s1 = xq + (size_t)b*NQ*DIM;
    float4* dst = (float4*)fb;
    const float4* a0 = (const float4*)s0;
    const float4* a1 = (const float4*)s1;
    const int n0 = NSUP*DIM/4, n1 = NQ*DIM/4;
    for (int t=tid; t<n0; t+=256) dst[t] = a0[t];
    for (int t=tid; t<n1; t+=256) dst[n0+t] = a1[t];
    float* pr = g_proto + (size_t)b*WAYS*DIM;
    for (int t=tid; t<WAYS*DIM; t+=256){
        int w = t/DIM, d = t-w*DIM;
        float a = 0.f;
        #pragma unroll
        for (int s=0;s<SHOT;s++) a += s0[(w*SHOT+s)*DIM + d];
        pr[t] = a*0.2f;
    }
}

// ---- K0b: one-time 100x100 exp(-lam*d2) block cache ----
__global__ void __launch_bounds__(256) k_gram0(){
    __shared__ float tile[64*TP];
    __shared__ float nd[112];
    int b = blockIdx.x, tid = threadIdx.x;
    int tx = tid & 15, ty = tid >> 4;
    const float* fb = g_feat + (size_t)b*N105*DIM;
    float acc[7][7];
    #pragma unroll
    for (int i=0;i<7;i++)
        #pragma unroll
        for (int j=0;j<7;j++) acc[i][j]=0.0f;
    for (int c=0;c<10;c++){
        for (int t=tid; t<N100*64; t+=256){
            int row = t>>6, k = t&63;
            tile[k*TP+row] = fb[(size_t)row*DIM + c*64 + k];
        }
        for (int t=tid; t<64*13; t+=256) tile[(t/13)*TP + 100 + (t%13)] = 0.0f;
        __syncthreads();
        #pragma unroll 4
        for (int k=0;k<64;k++){
            float av[7], bv[7];
            #pragma unroll
            for (int e=0;e<7;e++){ av[e]=tile[k*TP+ty+16*e]; bv[e]=tile[k*TP+tx+16*e]; }
            #pragma unroll
            for (int i=0;i<7;i++)
                #pragma unroll
                for (int j=0;j<7;j++) acc[i][j] += av[i]*bv[j];
        }
        __syncthreads();
    }
    if (tx==ty){
        #pragma unroll
        for (int e=0;e<7;e++) nd[ty+16*e] = acc[e][e];
    }
    __syncthreads();
    float* E = g_E100 + (size_t)b*N100*N100;
    #pragma unroll
    for (int i=0;i<7;i++){
        int r = ty + 16*i;
        if (r < N100){
            #pragma unroll
            for (int j=0;j<7;j++){
                int c = tx + 16*j;
                if (c < N100){
                    float d2 = fmaxf(nd[r]+nd[c]-2.0f*acc[i][j], 0.0f);
                    E[r*N100+c] = (r==c) ? 0.0f : expf(-LAMv*d2);
                }
            }
        }
    }
}

// ---- K1: M = exp(-lam * d2(queries, proto)) ----
__global__ void __launch_bounds__(256) k_dist_proto(){
    __shared__ float sp[WAYS*DIM];
    __shared__ float pn[WAYS];
    int b = blockIdx.x, tid = threadIdx.x;
    const float* pr = g_proto + (size_t)b*WAYS*DIM;
    for (int t=tid; t<WAYS*DIM; t+=256) sp[t] = pr[t];
    __syncthreads();
    int w = tid>>5, lane = tid&31;
    if (w < WAYS){
        float a=0.f;
        for (int d=lane; d<DIM; d+=32){ float v=sp[w*DIM+d]; a += v*v; }
        a = wredSum(a);
        if (lane==0) pn[w]=a;
    }
    __syncthreads();
    const float* fb = g_feat + (size_t)b*N105*DIM;
    for (int r=w; r<NQ; r+=8){
        const float* f = fb + (size_t)(NSUP+r)*DIM;
        float nf=0.f, dk[WAYS]={0,0,0,0,0};
        for (int d=lane; d<DIM; d+=32){
            float v = f[d];
            nf += v*v;
            #pragma unroll
            for (int k=0;k<WAYS;k++) dk[k] += v*sp[k*DIM+d];
        }
        nf = wredSum(nf);
        #pragma unroll
        for (int k=0;k<WAYS;k++) dk[k] = wredSum(dk[k]);
        if (lane < WAYS){
            float d2 = fmaxf(nf + pn[lane] - 2.0f*dk[lane], 0.0f);
            g_M[((size_t)b*NQ + r)*WAYS + lane] = expf(-LAMv*d2);
        }
    }
}

// ---- Sinkhorn phase A: exact trajectory, mark bad iters, store snapshots ----
template<int N, int NL>
__global__ void __launch_bounds__(256) k_sinkA(const int* __restrict__ ys, int slot){
    const int gw = (blockIdx.x*blockDim.x + threadIdx.x) >> 5;
    const int lane = threadIdx.x & 31;
    if (gw >= RUNS) return;
    const int b = gw;
    constexpr int J = (N+31)/32;
    const float cval = (float)(N/WAYS);
    const float* in = (N==NQ) ? (g_M + (size_t)b*NQ*WAYS) : (g_Z + (size_t)b*N105*WAYS);
    float p[J][WAYS];
    bool valid[J];
    #pragma unroll
    for (int j=0;j<J;j++){
        int r = lane + 32*j;
        valid[j] = (r < N);
        #pragma unroll
        for (int k=0;k<WAYS;k++) p[j][k] = valid[j] ? in[r*WAYS+k] : 0.0f;
    }
    int ycls = 0;
    const bool pin = (NL>0) && (lane < NL);
    if (pin) ycls = ys[b*NSUP + lane];

    float u[J];
    #pragma unroll
    for (int j=0;j<J;j++) u[j]=0.0f;
    int streak = 0, smax = 0;
    int* badp = g_bad + slot*1024;
    float* snapb = g_snap + (size_t)b*SNAPMAX*WAYS*128;

    for (int t=0; t<MAXIT; t++){
        if ((t&7)==0 && (t>>3)<SNAPMAX){
            int s = t>>3; smax = s;
            #pragma unroll
            for (int k=0;k<WAYS;k++)
                #pragma unroll
                for (int j=0;j<J;j++)
                    snapb[((size_t)s*WAYS+k)*128 + j*32 + lane] = p[j][k];
        }
        float rs[J]; float dvl = 0.0f;
        #pragma unroll
        for (int j=0;j<J;j++){
            rs[j] = p[j][0]+p[j][1]+p[j][2]+p[j][3]+p[j][4];
            if (valid[j]) dvl = fmaxf(dvl, fabsf(u[j]-rs[j]));
            u[j] = rs[j];
        }
        // row normalize
        #pragma unroll
        for (int j=0;j<J;j++) if (valid[j]){
            float f = 1.0f/rs[j];
            #pragma unroll
            for (int k=0;k<WAYS;k++) p[j][k] *= f;
        }
        // col partial sums
        float cs[WAYS];
        #pragma unroll
        for (int k=0;k<WAYS;k++){
            float a = 0.0f;
            #pragma unroll
            for (int j=0;j<J;j++) if (valid[j]) a += p[j][k];
            cs[k] = a;
        }
        // interleaved butterfly: 5 sums + 1 max in one pass
        #pragma unroll
        for (int o=16;o;o>>=1){
            dvl = fmaxf(dvl, __shfl_xor_sync(0xffffffffu, dvl, o));
            #pragma unroll
            for (int k=0;k<WAYS;k++) cs[k] += __shfl_xor_sync(0xffffffffu, cs[k], o);
        }
        #pragma unroll
        for (int k=0;k<WAYS;k++){
            float f = cval/cs[k];
            #pragma unroll
            for (int j=0;j<J;j++) if (valid[j]) p[j][k] *= f;
        }
        if (pin){
            #pragma unroll
            for (int k=0;k<WAYS;k++) p[0][k] = (k==ycls)?1.0f:0.0f;
        }
        if (dvl > EPSV){ if (lane==0) badp[t] = 1; streak = 0; }
        else if (++streak >= 32) break;
    }
    if (lane==0) g_nsnap[b] = smax;
}

// ---- Sinkhorn phase B: load snapshot at/below T, replay remainder ----
template<int N, int NL>
__global__ void __launch_bounds__(256) k_sinkB(const int* __restrict__ ys, int slot){
    const int gw = (blockIdx.x*blockDim.x + threadIdx.x) >> 5;
    const int lane = threadIdx.x & 31;
    if (gw >= RUNS) return;
    const int b = gw;
    constexpr int J = (N+31)/32;
    const float cval = (float)(N/WAYS);
    float* out = (N==NQ) ? (g_Z + ((size_t)b*N105 + NSUP)*WAYS) : (g_Z + (size_t)b*N105*WAYS);
    const int T = g_T[slot];
    int s = T>>3;
    int ns = g_nsnap[b];
    if (s > ns) s = ns;
    if (s > SNAPMAX-1) s = SNAPMAX-1;
    const int base = 8*s;
    const float* snapb = g_snap + (size_t)b*SNAPMAX*WAYS*128;
    float p[J][WAYS];
    bool valid[J];
    #pragma unroll
    for (int j=0;j<J;j++){
        valid[j] = (lane + 32*j) < N;
        #pragma unroll
        for (int k=0;k<WAYS;k++) p[j][k] = snapb[((size_t)s*WAYS+k)*128 + j*32 + lane];
    }
    int ycls = 0;
    const bool pin = (NL>0) && (lane < NL);
    if (pin) ycls = ys[b*NSUP + lane];

    for (int t=base; t<T; t++){
        float rs[J];
        #pragma unroll
        for (int j=0;j<J;j++){
            rs[j] = p[j][0]+p[j][1]+p[j][2]+p[j][3]+p[j][4];
            if (valid[j]){
                float f = 1.0f/rs[j];
                #pragma unroll
                for (int k=0;k<WAYS;k++) p[j][k] *= f;
            }
        }
        float cs[WAYS];
        #pragma unroll
        for (int k=0;k<WAYS;k++){
            float a = 0.0f;
            #pragma unroll
            for (int j=0;j<J;j++) if (valid[j]) a += p[j][k];
            cs[k] = a;
        }
        #pragma unroll
        for (int o=16;o;o>>=1){
            #pragma unroll
            for (int k=0;k<WAYS;k++) cs[k] += __shfl_xor_sync(0xffffffffu, cs[k], o);
        }
        #pragma unroll
        for (int k=0;k<WAYS;k++){
            float f = cval/cs[k];
            #pragma unroll
            for (int j=0;j<J;j++) if (valid[j]) p[j][k] *= f;
        }
        if (pin){
            #pragma unroll
            for (int k=0;k<WAYS;k++) p[0][k] = (k==ycls)?1.0f:0.0f;
        }
    }
    #pragma unroll
    for (int j=0;j<J;j++) if (valid[j]){
        int r = lane + 32*j;
        #pragma unroll
        for (int k=0;k<WAYS;k++) out[r*WAYS+k] = p[j][k];
    }
}

// ---- scan: T = first t with no run bad (exact while_loop stop) ----
__global__ void __launch_bounds__(256) k_scan(int slot){
    __shared__ int mn[256];
    int tid = threadIdx.x;
    const int* badp = g_bad + slot*1024;
    int best = MAXIT;
    for (int t=tid; t<MAXIT; t+=256) if (badp[t]==0 && t<best) best = t;
    mn[tid] = best;
    __syncthreads();
    for (int s=128; s; s>>=1){ if (tid<s) mn[tid] = min(mn[tid], mn[tid+s]); __syncthreads(); }
    if (tid==0) g_T[slot] = mn[0];
}

// ---- K3: entropy weighting, proto update, mask, write appended rows ----
__global__ void __launch_bounds__(256) k_update(const int* __restrict__ ys){
    __shared__ float z[N100][WAYS];
    __shared__ float ent[N100];
    __shared__ float S[WAYS];
    __shared__ float sp[WAYS*DIM];
    __shared__ float dpd[WAYS*WAYS];
    __shared__ float dpe[WAYS*WAYS];
    __shared__ float maskv[WAYS];
    __shared__ float omega_s;
    int b = blockIdx.x, tid = threadIdx.x;
    float* Zb = g_Z + (size_t)b*N105*WAYS;
    const float INVLOG5 = 0.6213349345596119f;
    if (tid < N100){
        if (tid < NSUP){
            int c = ys[b*NSUP + tid];
            #pragma unroll
            for (int k=0;k<WAYS;k++) z[tid][k] = (k==c)?1.0f:0.0f;
        } else {
            #pragma unroll
            for (int k=0;k<WAYS;k++) z[tid][k] = Zb[tid*WAYS+k];
        }
        float q[WAYS]; float s = 0.0f;
        #pragma unroll
        for (int k=0;k<WAYS;k++){ q[k] = z[tid][k] + 1e-12f; s += q[k]; }
        float H = 0.0f;
        #pragma unroll
        for (int k=0;k<WAYS;k++){ float pp = q[k]/s; H -= pp*logf(pp); }
        float e = H*INVLOG5;
        ent[tid] = e;
        float wgt = 1.0f - e;
        #pragma unroll
        for (int k=0;k<WAYS;k++) z[tid][k] *= wgt;
    }
    __syncthreads();
    if (tid < WAYS){
        float a = 0.0f;
        for (int i=0;i<N100;i++) a += z[i][tid];
        S[tid] = a;
    }
    if (tid == 128){
        float a = 0.0f;
        for (int i=0;i<N100;i++) a += ent[i];
        omega_s = a*0.01f;
    }
    __syncthreads();
    const float* fb = g_feat + (size_t)b*N105*DIM;
    float* prb = g_proto + (size_t)b*WAYS*DIM;
    for (int d=tid; d<DIM; d+=256){
        float acc[WAYS] = {0,0,0,0,0};
        for (int i=0;i<N100;i++){
            float f = fb[(size_t)i*DIM + d];
            #pragma unroll
            for (int k=0;k<WAYS;k++) acc[k] += z[i][k]*f;
        }
        #pragma unroll
        for (int k=0;k<WAYS;k++){
            float pv = 0.4f*prb[k*DIM+d] + 0.6f*(acc[k]/S[k]);
            prb[k*DIM+d] = pv;
            sp[k*DIM+d]  = pv;
        }
    }
    __syncthreads();
    int w = tid>>5, lane = tid&31;
    for (int pidx=w; pidx<WAYS*WAYS; pidx+=8){
        int a = pidx/WAYS, c = pidx%WAYS;
        float acc = 0.0f;
        for (int d=lane; d<DIM; d+=32) acc += sp[a*DIM+d]*sp[c*DIM+d];
        acc = wredSum(acc);
        if (lane==0) dpd[pidx] = acc;
    }
    __syncthreads();
    if (tid < WAYS*WAYS){
        int a = tid/WAYS, c = tid%WAYS;
        float d2 = fmaxf(dpd[a*WAYS+a] + dpd[c*WAYS+c] - 2.0f*dpd[tid], 0.0f);
        dpe[tid] = expf(-LAMv*d2);
    }
    __syncthreads();
    if (tid < WAYS){
        float q[WAYS]; float s = 0.0f;
        #pragma unroll
        for (int k=0;k<WAYS;k++){ q[k] = dpe[tid*WAYS+k] + 1e-12f; s += q[k]; }
        float H = 0.0f;
        #pragma unroll
        for (int k=0;k<WAYS;k++){ float pp = q[k]/s; H -= pp*logf(pp); }
        maskv[tid] = (H*INVLOG5 < omega_s) ? 1.0f : 0.0f;
    }
    __syncthreads();
    float* fwr = g_feat + (size_t)b*N105*DIM + (size_t)N100*DIM;
    for (int t=tid; t<WAYS*DIM; t+=256) fwr[t] = sp[t]*maskv[t/DIM];
    for (int t=tid; t<N100*WAYS; t+=256) Zb[t] = z[t/WAYS][t%WAYS];
    if (tid < WAYS*WAYS) Zb[N100*WAYS + tid] = dpe[tid]*maskv[tid/WAYS];
}

// ---- K4: strip + cached E100 -> A=I-aW -> LU solve (A X = Z) ----
__global__ void __launch_bounds__(256) k_graph_solve(){
    __shared__ float As[N105*N105];
    __shared__ float st[N105*WAYS];
    __shared__ float zz[N105*WAYS];
    __shared__ float nrm[N105];
    int b = blockIdx.x, tid = threadIdx.x;
    int w = tid>>5, lane = tid&31;
    const float* fb = g_feat + (size_t)b*N105*DIM;

    float* ap = As;
    for (int t=tid; t<WAYS*DIM; t+=256) ap[t] = fb[(size_t)N100*DIM + t];
    __syncthreads();

    for (int i=w; i<N105; i+=8){
        const float* f = fb + (size_t)i*DIM;
        float nf=0.f, dk[WAYS]={0,0,0,0,0};
        for (int d=lane; d<DIM; d+=32){
            float v = f[d];
            nf += v*v;
            #pragma unroll
            for (int p=0;p<WAYS;p++) dk[p] += v*ap[p*DIM+d];
        }
        nf = wredSum(nf);
        #pragma unroll
        for (int p=0;p<WAYS;p++) dk[p] = wredSum(dk[p]);
        if (lane==0){
            nrm[i] = nf;
            #pragma unroll
            for (int p=0;p<WAYS;p++) st[i*WAYS+p] = dk[p];
        }
    }
    __syncthreads();

    const float* E = g_E100 + (size_t)b*N100*N100;
    for (int t=tid; t<N105*N105; t+=256){
        int i = t/N105, j = t - i*N105;
        float v;
        if (i < N100 && j < N100){
            v = E[i*N100+j];
        } else if (i == j){
            v = 0.0f;
        } else {
            float dot = (j >= N100) ? st[i*WAYS + (j-N100)] : st[j*WAYS + (i-N100)];
            float d2 = fmaxf(nrm[i] + nrm[j] - 2.0f*dot, 0.0f);
            v = expf(-LAMv*d2);
        }
        As[t] = v;
    }
    float* Zb = g_Z + (size_t)b*N105*WAYS;
    for (int t=tid; t<N105*WAYS; t+=256) zz[t] = Zb[t];
    __syncthreads();

    if (tid < N105){
        float s = 0.0f;
        for (int j=0;j<N105;j++) s += As[tid*N105+j];
        nrm[tid] = rsqrtf(s);
    }
    __syncthreads();
    for (int t=tid; t<N105*N105; t+=256){
        int i = t/N105, j = t - i*N105;
        As[t] = ((i==j)?1.0f:0.0f) - 0.7f*nrm[i]*nrm[j]*As[t];
    }
    __syncthreads();

    float* colL = st;
    for (int k=0;k<N105-1;k++){
        float invP = 1.0f/As[k*N105+k];
        for (int i=k+1+tid; i<N105; i+=256) colL[i] = As[i*N105+k]*invP;
        __syncthreads();
        int jb = k+1+lane;
        float pr[4];
        #pragma unroll
        for (int m=0;m<4;m++){ int j = jb+32*m; pr[m] = (j<N105)? As[k*N105+j] : 0.0f; }
        float pz = (lane<WAYS)? zz[k*WAYS+lane] : 0.0f;
        for (int i=k+1+w; i<N105; i+=8){
            float l = colL[i];
            #pragma unroll
            for (int m=0;m<4;m++){ int j = jb+32*m; if (j<N105) As[i*N105+j] -= l*pr[m]; }
            if (lane<WAYS) zz[i*WAYS+lane] -= l*pz;
        }
        __syncthreads();
    }
    for (int k=N105-1;k>=0;k--){
        if (tid < WAYS) zz[k*WAYS+tid] /= As[k*N105+k];
        __syncthreads();
        for (int t=tid; t<k*WAYS; t+=256){
            int i=t/WAYS, m=t-i*WAYS;
            zz[i*WAYS+m] -= As[i*N105+k]*zz[k*WAYS+m];
        }
        __syncthreads();
    }
    for (int t=tid; t<N105*WAYS; t+=256) Zb[t] = zz[t];
}

// ---- K5: accuracy over queries ----
__global__ void __launch_bounds__(128) k_acc(const int* __restrict__ yq, float* __restrict__ out){
    __shared__ int cnt[128];
    int b = blockIdx.x, tid = threadIdx.x;
    int m = 0;
    if (tid < NQ){
        const float* zr = g_Z + ((size_t)b*N105 + NSUP + tid)*WAYS;
        float best = zr[0]; int bi = 0;
        #pragma unroll
        for (int k=1;k<WAYS;k++){ if (zr[k] > best){ best = zr[k]; bi = k; } }
        m = (bi == yq[b*NQ + tid]) ? 1 : 0;
    }
    cnt[tid] = m;
    __syncthreads();
    for (int s=64; s; s>>=1){ if (tid < s) cnt[tid] += cnt[tid+s]; __syncthreads(); }
    if (tid==0) out[b] = (float)cnt[0] / 75.0f;
}

extern "C" void kernel_launch(void* const* d_in, const int* in_sizes, int n_in,
                              void* d_out, int out_size){
    const float* xs = (const float*)d_in[0];
    const float* xq = (const float*)d_in[1];
    const int*   ys = (const int*)d_in[2];
    const int*   yq = (const int*)d_in[3];
    float* out = (float*)d_out;
    (void)in_sizes; (void)n_in; (void)out_size;

    k_init<<<RUNS,256>>>(xs, xq);
    k_gram0<<<RUNS,256>>>();
    for (int e=0;e<3;e++){
        k_dist_proto<<<RUNS,256>>>();
        k_sinkA<NQ,0><<<64,256>>>(ys, 2*e);
        k_scan<<<1,256>>>(2*e);
        k_sinkB<NQ,0><<<64,256>>>(ys, 2*e);
        k_update<<<RUNS,256>>>(ys);
        k_graph_solve<<<RUNS,256>>>();
        k_sinkA<N105,NSUP><<<64,256>>>(ys, 2*e+1);
        k_scan<<<1,256>>>(2*e+1);
        k_sinkB<N105,NSUP><<<64,256>>>(ys, 2*e+1);
    }
    k_acc<<<RUNS,128>>>(yq, out);
}

// round 9
// speedup vs baseline: 1.0807x; 1.0807x over previous
#include <cuda_runtime.h>
#include <math.h>

#define RUNS 512
#define WAYS 5
#define SHOT 5
#define NSUP 25
#define NQ   75
#define N100 100
#define N105 105
#define DIM  640
#define LAMv 10.0f
#define EPSV 0.001f
#define MAXIT 1000
#define TPW 130

typedef unsigned long long u64t;
__device__ __forceinline__ u64t pk2(float lo, float hi){
    u64t r; asm("mov.b64 %0,{%1,%2};" : "=l"(r) : "f"(lo), "f"(hi)); return r;
}
__device__ __forceinline__ float2 upk2(u64t v){
    float2 r; asm("mov.b64 {%0,%1},%2;" : "=f"(r.x), "=f"(r.y) : "l"(v)); return r;
}
__device__ __forceinline__ void ffma2(u64t &acc, u64t a, u64t b){
    asm("fma.rn.f32x2 %0,%1,%2,%0;" : "+l"(acc) : "l"(a), "l"(b));
}

__device__ float g_ap[(size_t)RUNS*WAYS*DIM];      // appended masked protos (rows 100..104)
__device__ float g_proto[(size_t)RUNS*WAYS*DIM];
__device__ float g_M[(size_t)RUNS*NQ*WAYS];
__device__ float g_Z[(size_t)RUNS*N105*WAYS];
__device__ float g_E100[(size_t)RUNS*N100*N100];
__device__ int   g_T[8];
__device__ int   g_bad[6*1024];

__device__ __forceinline__ float wredSum(float v){
    #pragma unroll
    for (int o=16;o;o>>=1) v += __shfl_xor_sync(0xffffffffu, v, o);
    return v;
}

// ---- K0: initial prototypes, reset T/bad (no feature copy) ----
__global__ void __launch_bounds__(256) k_init(const float* __restrict__ xs){
    int b = blockIdx.x, tid = threadIdx.x;
    if (b==0){
        if (tid<8) g_T[tid]=0;
        for (int t=tid; t<6*1024; t+=256) g_bad[t]=0;
    }
    const float* s0 = xs + (size_t)b*NSUP*DIM;
    float* pr = g_proto + (size_t)b*WAYS*DIM;
    for (int t=tid; t<WAYS*DIM; t+=256){
        int w = t/DIM, d = t-w*DIM;
        float a = 0.f;
        #pragma unroll
        for (int s=0;s<SHOT;s++) a += s0[(w*SHOT+s)*DIM + d];
        pr[t] = a*0.2f;
    }
}

// ---- K0b: one-time 100x100 exp(-lam*d2) cache, FFMA2 inner loop ----
__global__ void __launch_bounds__(256) k_gram0(const float* __restrict__ xs,
                                               const float* __restrict__ xq){
    __shared__ float tile[64*TPW];   // 33280 B, cols 0..99 = feature rows, rest zero
    __shared__ float nd[128];
    int b = blockIdx.x, tid = threadIdx.x;
    int tx = tid & 15, ty = tid >> 4;
    u64t acc2[7][4];
    #pragma unroll
    for (int i=0;i<7;i++)
        #pragma unroll
        for (int e=0;e<4;e++) acc2[i][e] = pk2(0.f,0.f);
    for (int t=tid; t<64*TPW; t+=256) tile[t]=0.f;
    __syncthreads();
    const float* xsb = xs + (size_t)b*NSUP*DIM;
    const float* xqb = xq + (size_t)b*NQ*DIM;
    for (int c=0;c<10;c++){
        for (int t=tid; t<N100*64; t+=256){
            int row = t>>6, k = t&63;
            const float* fr = (row<NSUP) ? (xsb + (size_t)row*DIM)
                                         : (xqb + (size_t)(row-NSUP)*DIM);
            tile[k*TPW+row] = fr[c*64+k];
        }
        __syncthreads();
        #pragma unroll 2
        for (int k=0;k<64;k++){
            const float* tk = &tile[k*TPW];
            u64t ap[7], bp[4];
            #pragma unroll
            for (int i=0;i<7;i++){ float a = tk[ty+16*i]; ap[i]=pk2(a,a); }
            #pragma unroll
            for (int e=0;e<4;e++){
                float2 bv = *(const float2*)(tk + 2*tx + 32*e);
                bp[e] = pk2(bv.x, bv.y);
            }
            #pragma unroll
            for (int i=0;i<7;i++)
                #pragma unroll
                for (int e=0;e<4;e++) ffma2(acc2[i][e], ap[i], bp[e]);
        }
        __syncthreads();
    }
    // extract diagonal norms
    #pragma unroll
    for (int i=0;i<7;i++){
        int r = ty+16*i;
        #pragma unroll
        for (int e=0;e<4;e++){
            int c = 2*tx+32*e;
            if (c==r || c+1==r){
                float2 g = upk2(acc2[i][e]);
                if (c==r)   nd[r] = g.x;
                if (c+1==r) nd[r] = g.y;
            }
        }
    }
    __syncthreads();
    float* E = g_E100 + (size_t)b*N100*N100;
    #pragma unroll
    for (int i=0;i<7;i++){
        int r = ty+16*i;
        if (r < N100){
            float nr = nd[r];
            #pragma unroll
            for (int e=0;e<4;e++){
                int c = 2*tx+32*e;
                float2 g = upk2(acc2[i][e]);
                if (c < N100){
                    float d2 = fmaxf(nr+nd[c]-2.0f*g.x, 0.0f);
                    E[r*N100+c] = (r==c)?0.0f:__expf(-LAMv*d2);
                }
                if (c+1 < N100){
                    float d2 = fmaxf(nr+nd[c+1]-2.0f*g.y, 0.0f);
                    E[r*N100+c+1] = (r==c+1)?0.0f:__expf(-LAMv*d2);
                }
            }
        }
    }
}

// ---- K1: M = exp(-lam * d2(queries, proto)) ----
__global__ void __launch_bounds__(256) k_dist_proto(const float* __restrict__ xq){
    __shared__ float sp[WAYS*DIM];
    __shared__ float pn[WAYS];
    int b = blockIdx.x, tid = threadIdx.x;
    const float* pr = g_proto + (size_t)b*WAYS*DIM;
    for (int t=tid; t<WAYS*DIM; t+=256) sp[t] = pr[t];
    __syncthreads();
    int w = tid>>5, lane = tid&31;
    if (w < WAYS){
        float a=0.f;
        for (int d=lane; d<DIM; d+=32){ float v=sp[w*DIM+d]; a += v*v; }
        a = wredSum(a);
        if (lane==0) pn[w]=a;
    }
    __syncthreads();
    const float* xqb = xq + (size_t)b*NQ*DIM;
    for (int r=w; r<NQ; r+=8){
        const float* f = xqb + (size_t)r*DIM;
        float nf=0.f, dk[WAYS]={0,0,0,0,0};
        for (int d=lane; d<DIM; d+=32){
            float v = f[d];
            nf += v*v;
            #pragma unroll
            for (int k=0;k<WAYS;k++) dk[k] += v*sp[k*DIM+d];
        }
        nf = wredSum(nf);
        #pragma unroll
        for (int k=0;k<WAYS;k++) dk[k] = wredSum(dk[k]);
        if (lane < WAYS){
            float d2 = fmaxf(nf + pn[lane] - 2.0f*dk[lane], 0.0f);
            g_M[((size_t)b*NQ + r)*WAYS + lane] = __expf(-LAMv*d2);
        }
    }
}

// ---- Sinkhorn, warp per run. phaseB=0: mark bad iters; 1: apply T ----
template<int N, int NL>
__global__ void __launch_bounds__(256) k_sinkhorn(const int* __restrict__ ys,
                                                  int slot, int phaseB){
    const int gw = (blockIdx.x*blockDim.x + threadIdx.x) >> 5;
    const int lane = threadIdx.x & 31;
    if (gw >= RUNS) return;
    const int b = gw;
    constexpr int J = (N+31)/32;
    const float cval = (float)(N/WAYS);
    const float* in; float* out;
    if (N == NQ){ in = g_M + (size_t)b*NQ*WAYS;   out = g_Z + ((size_t)b*N105 + NSUP)*WAYS; }
    else        { in = g_Z + (size_t)b*N105*WAYS; out = g_Z + (size_t)b*N105*WAYS; }
    float p[J][WAYS];
    bool valid[J];
    #pragma unroll
    for (int j=0;j<J;j++){
        int r = lane + 32*j;
        valid[j] = (r < N);
        #pragma unroll
        for (int k=0;k<WAYS;k++) p[j][k] = valid[j] ? in[r*WAYS+k] : 0.0f;
    }
    int ycls = 0;
    const bool pin = (NL>0) && (lane < NL);
    if (pin) ycls = ys[b*NSUP + lane];

    if (!phaseB){
        float u[J];
        #pragma unroll
        for (int j=0;j<J;j++) u[j]=0.0f;
        int streak = 0;
        int* badp = g_bad + slot*1024;
        for (int t=0; t<MAXIT; t++){
            float rs[J]; float dvl = 0.0f;
            #pragma unroll
            for (int j=0;j<J;j++){
                rs[j] = p[j][0]+p[j][1]+p[j][2]+p[j][3]+p[j][4];
                if (valid[j]) dvl = fmaxf(dvl, fabsf(u[j]-rs[j]));
                u[j] = rs[j];
            }
            #pragma unroll
            for (int j=0;j<J;j++) if (valid[j]){
                float f = 1.0f/rs[j];
                #pragma unroll
                for (int k=0;k<WAYS;k++) p[j][k] *= f;
            }
            float cs[WAYS];
            #pragma unroll
            for (int k=0;k<WAYS;k++){
                float a = 0.0f;
                #pragma unroll
                for (int j=0;j<J;j++) if (valid[j]) a += p[j][k];
                cs[k] = a;
            }
            #pragma unroll
            for (int o=16;o;o>>=1){
                dvl = fmaxf(dvl, __shfl_xor_sync(0xffffffffu, dvl, o));
                #pragma unroll
                for (int k=0;k<WAYS;k++) cs[k] += __shfl_xor_sync(0xffffffffu, cs[k], o);
            }
            #pragma unroll
            for (int k=0;k<WAYS;k++){
                float f = cval/cs[k];
                #pragma unroll
                for (int j=0;j<J;j++) if (valid[j]) p[j][k] *= f;
            }
            if (pin){
                #pragma unroll
                for (int k=0;k<WAYS;k++) p[0][k] = (k==ycls)?1.0f:0.0f;
            }
            if (dvl > EPSV){ if (lane==0) badp[t] = 1; streak = 0; }
            else if (++streak >= 12) break;
        }
    } else {
        const int T = g_T[slot];
        for (int t=0; t<T; t++){
            float rs[J];
            #pragma unroll
            for (int j=0;j<J;j++){
                rs[j] = p[j][0]+p[j][1]+p[j][2]+p[j][3]+p[j][4];
                if (valid[j]){
                    float f = 1.0f/rs[j];
                    #pragma unroll
                    for (int k=0;k<WAYS;k++) p[j][k] *= f;
                }
            }
            float cs[WAYS];
            #pragma unroll
            for (int k=0;k<WAYS;k++){
                float a = 0.0f;
                #pragma unroll
                for (int j=0;j<J;j++) if (valid[j]) a += p[j][k];
                cs[k] = a;
            }
            #pragma unroll
            for (int o=16;o;o>>=1){
                #pragma unroll
                for (int k=0;k<WAYS;k++) cs[k] += __shfl_xor_sync(0xffffffffu, cs[k], o);
            }
            #pragma unroll
            for (int k=0;k<WAYS;k++){
                float f = cval/cs[k];
                #pragma unroll
                for (int j=0;j<J;j++) if (valid[j]) p[j][k] *= f;
            }
            if (pin){
                #pragma unroll
                for (int k=0;k<WAYS;k++) p[0][k] = (k==ycls)?1.0f:0.0f;
            }
        }
        #pragma unroll
        for (int j=0;j<J;j++) if (valid[j]){
            int r = lane + 32*j;
            #pragma unroll
            for (int k=0;k<WAYS;k++) out[r*WAYS+k] = p[j][k];
        }
    }
}

// ---- scan: T = first t with no run bad ----
__global__ void __launch_bounds__(256) k_scan(int slot){
    __shared__ int mn[256];
    int tid = threadIdx.x;
    const int* badp = g_bad + slot*1024;
    int best = MAXIT;
    for (int t=tid; t<MAXIT; t+=256) if (badp[t]==0 && t<best) best = t;
    mn[tid] = best;
    __syncthreads();
    for (int s=128; s; s>>=1){ if (tid<s) mn[tid] = min(mn[tid], mn[tid+s]); __syncthreads(); }
    if (tid==0) g_T[slot] = mn[0];
}

// ---- K3: entropy weighting, proto update, mask, write appended rows ----
__global__ void __launch_bounds__(256) k_update(const float* __restrict__ xs,
                                                const float* __restrict__ xq,
                                                const int* __restrict__ ys){
    __shared__ float z8[N100][8];
    __shared__ float ent[N100];
    __shared__ float S[WAYS];
    __shared__ float sp[WAYS*DIM];
    __shared__ float dpd[WAYS*WAYS];
    __shared__ float dpe[WAYS*WAYS];
    __shared__ float maskv[WAYS];
    __shared__ float omega_s;
    int b = blockIdx.x, tid = threadIdx.x;
    float* Zb = g_Z + (size_t)b*N105*WAYS;
    const float INVLOG5 = 0.6213349345596119f;
    if (tid < N100){
        float zv[WAYS];
        if (tid < NSUP){
            int c = ys[b*NSUP + tid];
            #pragma unroll
            for (int k=0;k<WAYS;k++) zv[k] = (k==c)?1.0f:0.0f;
        } else {
            #pragma unroll
            for (int k=0;k<WAYS;k++) zv[k] = Zb[tid*WAYS+k];
        }
        float q[WAYS]; float s = 0.0f;
        #pragma unroll
        for (int k=0;k<WAYS;k++){ q[k] = zv[k] + 1e-12f; s += q[k]; }
        float H = 0.0f;
        #pragma unroll
        for (int k=0;k<WAYS;k++){ float pp = q[k]/s; H -= pp*logf(pp); }
        float e = H*INVLOG5;
        ent[tid] = e;
        float wgt = 1.0f - e;
        #pragma unroll
        for (int k=0;k<WAYS;k++) z8[tid][k] = zv[k]*wgt;
        z8[tid][5]=0.f; z8[tid][6]=0.f; z8[tid][7]=0.f;
    }
    __syncthreads();
    if (tid < WAYS){
        float a = 0.0f;
        for (int i=0;i<N100;i++) a += z8[i][tid];
        S[tid] = a;
    }
    if (tid == 128){
        float a = 0.0f;
        for (int i=0;i<N100;i++) a += ent[i];
        omega_s = a*0.01f;
    }
    __syncthreads();
    const float* xsb = xs + (size_t)b*NSUP*DIM;
    const float* xqb = xq + (size_t)b*NQ*DIM;
    float* prb = g_proto + (size_t)b*WAYS*DIM;
    for (int d=tid; d<DIM; d+=256){
        float acc[WAYS] = {0,0,0,0,0};
        #pragma unroll 5
        for (int i=0;i<NSUP;i++){
            float f = xsb[(size_t)i*DIM + d];
            float4 zv = *(const float4*)&z8[i][0];
            float z4 = z8[i][4];
            acc[0] += zv.x*f; acc[1] += zv.y*f; acc[2] += zv.z*f;
            acc[3] += zv.w*f; acc[4] += z4*f;
        }
        #pragma unroll 5
        for (int i=0;i<NQ;i++){
            float f = xqb[(size_t)i*DIM + d];
            float4 zv = *(const float4*)&z8[NSUP+i][0];
            float z4 = z8[NSUP+i][4];
            acc[0] += zv.x*f; acc[1] += zv.y*f; acc[2] += zv.z*f;
            acc[3] += zv.w*f; acc[4] += z4*f;
        }
        #pragma unroll
        for (int k=0;k<WAYS;k++){
            float pv = 0.4f*prb[k*DIM+d] + 0.6f*(acc[k]/S[k]);
            prb[k*DIM+d] = pv;
            sp[k*DIM+d]  = pv;
        }
    }
    __syncthreads();
    int w = tid>>5, lane = tid&31;
    for (int pidx=w; pidx<WAYS*WAYS; pidx+=8){
        int a = pidx/WAYS, c = pidx%WAYS;
        float acc = 0.0f;
        for (int d=lane; d<DIM; d+=32) acc += sp[a*DIM+d]*sp[c*DIM+d];
        acc = wredSum(acc);
        if (lane==0) dpd[pidx] = acc;
    }
    __syncthreads();
    if (tid < WAYS*WAYS){
        int a = tid/WAYS, c = tid%WAYS;
        float d2 = fmaxf(dpd[a*WAYS+a] + dpd[c*WAYS+c] - 2.0f*dpd[tid], 0.0f);
        dpe[tid] = __expf(-LAMv*d2);
    }
    __syncthreads();
    if (tid < WAYS){
        float q[WAYS]; float s = 0.0f;
        #pragma unroll
        for (int k=0;k<WAYS;k++){ q[k] = dpe[tid*WAYS+k] + 1e-12f; s += q[k]; }
        float H = 0.0f;
        #pragma unroll
        for (int k=0;k<WAYS;k++){ float pp = q[k]/s; H -= pp*logf(pp); }
        maskv[tid] = (H*INVLOG5 < omega_s) ? 1.0f : 0.0f;
    }
    __syncthreads();
    float* fwr = g_ap + (size_t)b*WAYS*DIM;
    for (int t=tid; t<WAYS*DIM; t+=256) fwr[t] = sp[t]*maskv[t/DIM];
    for (int t=tid; t<N100*WAYS; t+=256) Zb[t] = z8[t/WAYS][t%WAYS];
    if (tid < WAYS*WAYS) Zb[N100*WAYS + tid] = dpe[tid]*maskv[tid/WAYS];
}

// ---- K4: strip + cached E100 -> A=I-aW -> LU solve (A X = Z) ----
__global__ void __launch_bounds__(256) k_graph_solve(const float* __restrict__ xs,
                                                     const float* __restrict__ xq){
    __shared__ float As[N105*N105];
    __shared__ float st[N105*WAYS];
    __shared__ float zz[N105*WAYS];
    __shared__ float nrm[N105];
    int b = blockIdx.x, tid = threadIdx.x;
    int w = tid>>5, lane = tid&31;
    const float* xsb = xs + (size_t)b*NSUP*DIM;
    const float* xqb = xq + (size_t)b*NQ*DIM;
    const float* apg = g_ap + (size_t)b*WAYS*DIM;

    float* ap = As;   // temp: protos in smem
    for (int t=tid; t<WAYS*DIM; t+=256) ap[t] = apg[t];
    __syncthreads();

    for (int i=w; i<N105; i+=8){
        const float* f = (i<NSUP) ? (xsb + (size_t)i*DIM)
                       : (i<N100) ? (xqb + (size_t)(i-NSUP)*DIM)
                                  : (apg + (size_t)(i-N100)*DIM);
        float nf=0.f, dk[WAYS]={0,0,0,0,0};
        for (int d=lane; d<DIM; d+=32){
            float v = f[d];
            nf += v*v;
            #pragma unroll
            for (int p=0;p<WAYS;p++) dk[p] += v*ap[p*DIM+d];
        }
        #pragma unroll
        for (int o=16;o;o>>=1){
            nf += __shfl_xor_sync(0xffffffffu, nf, o);
            #pragma unroll
            for (int p=0;p<WAYS;p++) dk[p] += __shfl_xor_sync(0xffffffffu, dk[p], o);
        }
        if (lane==0){
            nrm[i] = nf;
            #pragma unroll
            for (int p=0;p<WAYS;p++) st[i*WAYS+p] = dk[p];
        }
    }
    __syncthreads();

    const float* E = g_E100 + (size_t)b*N100*N100;
    for (int t=tid; t<N105*N105; t+=256){
        int i = t/N105, j = t - i*N105;
        float v;
        if (i < N100 && j < N100){
            v = E[i*N100+j];
        } else if (i == j){
            v = 0.0f;
        } else {
            float dot = (j >= N100) ? st[i*WAYS + (j-N100)] : st[j*WAYS + (i-N100)];
            float d2 = fmaxf(nrm[i] + nrm[j] - 2.0f*dot, 0.0f);
            v = __expf(-LAMv*d2);
        }
        As[t] = v;
    }
    float* Zb = g_Z + (size_t)b*N105*WAYS;
    for (int t=tid; t<N105*WAYS; t+=256) zz[t] = Zb[t];
    __syncthreads();

    if (tid < N105){
        float s = 0.0f;
        for (int j=0;j<N105;j++) s += As[tid*N105+j];
        nrm[tid] = rsqrtf(s);
    }
    __syncthreads();
    for (int t=tid; t<N105*N105; t+=256){
        int i = t/N105, j = t - i*N105;
        As[t] = ((i==j)?1.0f:0.0f) - 0.7f*nrm[i]*nrm[j]*As[t];
    }
    __syncthreads();

    float* colL = st;
    for (int k=0;k<N105-1;k++){
        float invP = 1.0f/As[k*N105+k];
        for (int i=k+1+tid; i<N105; i+=256) colL[i] = As[i*N105+k]*invP;
        __syncthreads();
        int jb = k+1+lane;
        float pr[4];
        #pragma unroll
        for (int m=0;m<4;m++){ int j = jb+32*m; pr[m] = (j<N105)? As[k*N105+j] : 0.0f; }
        float pz = (lane<WAYS)? zz[k*WAYS+lane] : 0.0f;
        for (int i=k+1+w; i<N105; i+=8){
            float l = colL[i];
            #pragma unroll
            for (int m=0;m<4;m++){ int j = jb+32*m; if (j<N105) As[i*N105+j] -= l*pr[m]; }
            if (lane<WAYS) zz[i*WAYS+lane] -= l*pz;
        }
        __syncthreads();
    }
    for (int k=N105-1;k>=0;k--){
        if (tid < WAYS) zz[k*WAYS+tid] /= As[k*N105+k];
        __syncthreads();
        for (int t=tid; t<k*WAYS; t+=256){
            int i=t/WAYS, m=t-i*WAYS;
            zz[i*WAYS+m] -= As[i*N105+k]*zz[k*WAYS+m];
        }
        __syncthreads();
    }
    for (int t=tid; t<N105*WAYS; t+=256) Zb[t] = zz[t];
}

// ---- K5: accuracy over queries ----
__global__ void __launch_bounds__(128) k_acc(const int* __restrict__ yq, float* __restrict__ out){
    __shared__ int cnt[128];
    int b = blockIdx.x, tid = threadIdx.x;
    int m = 0;
    if (tid < NQ){
        const float* zr = g_Z + ((size_t)b*N105 + NSUP + tid)*WAYS;
        float best = zr[0]; int bi = 0;
        #pragma unroll
        for (int k=1;k<WAYS;k++){ if (zr[k] > best){ best = zr[k]; bi = k; } }
        m = (bi == yq[b*NQ + tid]) ? 1 : 0;
    }
    cnt[tid] = m;
    __syncthreads();
    for (int s=64; s; s>>=1){ if (tid < s) cnt[tid] += cnt[tid+s]; __syncthreads(); }
    if (tid==0) out[b] = (float)cnt[0] / 75.0f;
}

extern "C" void kernel_launch(void* const* d_in, const int* in_sizes, int n_in,
                              void* d_out, int out_size){
    const float* xs = (const float*)d_in[0];
    const float* xq = (const float*)d_in[1];
    const int*   ys = (const int*)d_in[2];
    const int*   yq = (const int*)d_in[3];
    float* out = (float*)d_out;
    (void)in_sizes; (void)n_in; (void)out_size;

    k_init<<<RUNS,256>>>(xs);
    k_gram0<<<RUNS,256>>>(xs, xq);
    for (int e=0;e<3;e++){
        k_dist_proto<<<RUNS,256>>>(xq);
        k_sinkhorn<NQ,0><<<64,256>>>(ys, 2*e, 0);
        k_scan<<<1,256>>>(2*e);
        k_sinkhorn<NQ,0><<<64,256>>>(ys, 2*e, 1);
        k_update<<<RUNS,256>>>(xs, xq, ys);
        k_graph_solve<<<RUNS,256>>>(xs, xq);
        k_sinkhorn<N105,NSUP><<<64,256>>>(ys, 2*e+1, 0);
        k_scan<<<1,256>>>(2*e+1);
        k_sinkhorn<N105,NSUP><<<64,256>>>(ys, 2*e+1, 1);
    }
    k_acc<<<RUNS,128>>>(yq, out);
}

// round 10
// speedup vs baseline: 1.2943x; 1.1977x over previous
#include <cuda_runtime.h>
#include <math.h>

#define RUNS 512
#define WAYS 5
#define SHOT 5
#define NSUP 25
#define NQ   75
#define N100 100
#define N105 105
#define DIM  640
#define LAMv 10.0f
#define EPSV 0.001f
#define MAXIT 1000
#define TPW 130

typedef unsigned long long u64t;
__device__ __forceinline__ u64t pk2(float lo, float hi){
    u64t r; asm("mov.b64 %0,{%1,%2};" : "=l"(r) : "f"(lo), "f"(hi)); return r;
}
__device__ __forceinline__ float2 upk2(u64t v){
    float2 r; asm("mov.b64 {%0,%1},%2;" : "=f"(r.x), "=f"(r.y) : "l"(v)); return r;
}
__device__ __forceinline__ void ffma2(u64t &acc, u64t a, u64t b){
    asm("fma.rn.f32x2 %0,%1,%2,%0;" : "+l"(acc) : "l"(a), "l"(b));
}

__device__ float g_ap[(size_t)RUNS*WAYS*DIM];
__device__ float g_proto[(size_t)RUNS*WAYS*DIM];
__device__ float g_M[(size_t)RUNS*NQ*WAYS];
__device__ float g_Z[(size_t)RUNS*N105*WAYS];
__device__ float g_E100[(size_t)RUNS*N100*N100];
__device__ int   g_bad[6*1024];

__device__ __forceinline__ float wredSum(float v){
    #pragma unroll
    for (int o=16;o;o>>=1) v += __shfl_xor_sync(0xffffffffu, v, o);
    return v;
}

// ---- K0: initial prototypes, reset bad flags ----
__global__ void __launch_bounds__(256) k_init(const float* __restrict__ xs){
    int b = blockIdx.x, tid = threadIdx.x;
    if (b==0){
        for (int t=tid; t<6*1024; t+=256) g_bad[t]=0;
    }
    const float* s0 = xs + (size_t)b*NSUP*DIM;
    float* pr = g_proto + (size_t)b*WAYS*DIM;
    for (int t=tid; t<WAYS*DIM; t+=256){
        int w = t/DIM, d = t-w*DIM;
        float a = 0.f;
        #pragma unroll
        for (int s=0;s<SHOT;s++) a += s0[(w*SHOT+s)*DIM + d];
        pr[t] = a*0.2f;
    }
}

// ---- one-time 100x100 exp(-lam*d2) cache, FFMA2 inner loop ----
__global__ void __launch_bounds__(256) k_gram0(const float* __restrict__ xs,
                                               const float* __restrict__ xq){
    __shared__ float tile[64*TPW];
    __shared__ float nd[128];
    int b = blockIdx.x, tid = threadIdx.x;
    int tx = tid & 15, ty = tid >> 4;
    u64t acc2[7][4];
    #pragma unroll
    for (int i=0;i<7;i++)
        #pragma unroll
        for (int e=0;e<4;e++) acc2[i][e] = pk2(0.f,0.f);
    for (int t=tid; t<64*TPW; t+=256) tile[t]=0.f;
    __syncthreads();
    const float* xsb = xs + (size_t)b*NSUP*DIM;
    const float* xqb = xq + (size_t)b*NQ*DIM;
    for (int c=0;c<10;c++){
        for (int t=tid; t<N100*64; t+=256){
            int row = t>>6, k = t&63;
            const float* fr = (row<NSUP) ? (xsb + (size_t)row*DIM)
                                         : (xqb + (size_t)(row-NSUP)*DIM);
            tile[k*TPW+row] = fr[c*64+k];
        }
        __syncthreads();
        #pragma unroll 2
        for (int k=0;k<64;k++){
            const float* tk = &tile[k*TPW];
            u64t ap[7], bp[4];
            #pragma unroll
            for (int i=0;i<7;i++){ float a = tk[ty+16*i]; ap[i]=pk2(a,a); }
            #pragma unroll
            for (int e=0;e<4;e++){
                float2 bv = *(const float2*)(tk + 2*tx + 32*e);
                bp[e] = pk2(bv.x, bv.y);
            }
            #pragma unroll
            for (int i=0;i<7;i++)
                #pragma unroll
                for (int e=0;e<4;e++) ffma2(acc2[i][e], ap[i], bp[e]);
        }
        __syncthreads();
    }
    #pragma unroll
    for (int i=0;i<7;i++){
        int r = ty+16*i;
        #pragma unroll
        for (int e=0;e<4;e++){
            int c = 2*tx+32*e;
            if (c==r || c+1==r){
                float2 g = upk2(acc2[i][e]);
                if (c==r)   nd[r] = g.x;
                if (c+1==r) nd[r] = g.y;
            }
        }
    }
    __syncthreads();
    float* E = g_E100 + (size_t)b*N100*N100;
    #pragma unroll
    for (int i=0;i<7;i++){
        int r = ty+16*i;
        if (r < N100){
            float nr = nd[r];
            #pragma unroll
            for (int e=0;e<4;e++){
                int c = 2*tx+32*e;
                float2 g = upk2(acc2[i][e]);
                if (c < N100){
                    float d2 = fmaxf(nr+nd[c]-2.0f*g.x, 0.0f);
                    E[r*N100+c] = (r==c)?0.0f:__expf(-LAMv*d2);
                }
                if (c+1 < N100){
                    float d2 = fmaxf(nr+nd[c+1]-2.0f*g.y, 0.0f);
                    E[r*N100+c+1] = (r==c+1)?0.0f:__expf(-LAMv*d2);
                }
            }
        }
    }
}

// ---- M = exp(-lam * d2(queries, proto)) ----
__global__ void __launch_bounds__(256) k_dist_proto(const float* __restrict__ xq){
    __shared__ float sp[WAYS*DIM];
    __shared__ float pn[WAYS];
    int b = blockIdx.x, tid = threadIdx.x;
    const float* pr = g_proto + (size_t)b*WAYS*DIM;
    for (int t=tid; t<WAYS*DIM; t+=256) sp[t] = pr[t];
    __syncthreads();
    int w = tid>>5, lane = tid&31;
    if (w < WAYS){
        float a=0.f;
        for (int d=lane; d<DIM; d+=32){ float v=sp[w*DIM+d]; a += v*v; }
        a = wredSum(a);
        if (lane==0) pn[w]=a;
    }
    __syncthreads();
    const float* xqb = xq + (size_t)b*NQ*DIM;
    for (int r=w; r<NQ; r+=8){
        const float* f = xqb + (size_t)r*DIM;
        float nf=0.f, dk[WAYS]={0,0,0,0,0};
        for (int d=lane; d<DIM; d+=32){
            float v = f[d];
            nf += v*v;
            #pragma unroll
            for (int k=0;k<WAYS;k++) dk[k] += v*sp[k*DIM+d];
        }
        nf = wredSum(nf);
        #pragma unroll
        for (int k=0;k<WAYS;k++) dk[k] = wredSum(dk[k]);
        if (lane < WAYS){
            float d2 = fmaxf(nf + pn[lane] - 2.0f*dk[lane], 0.0f);
            g_M[((size_t)b*NQ + r)*WAYS + lane] = __expf(-LAMv*d2);
        }
    }
}

// ---- Sinkhorn, warp per run. phaseB=0: mark bad iters; 1: scan T + apply ----
template<int N, int NL>
__global__ void __launch_bounds__(256) k_sinkhorn(const int* __restrict__ ys,
                                                  int slot, int phaseB){
    const int gw = (blockIdx.x*blockDim.x + threadIdx.x) >> 5;
    const int lane = threadIdx.x & 31;
    if (gw >= RUNS) return;
    const int b = gw;
    constexpr int J = (N+31)/32;
    const float cval = (float)(N/WAYS);
    const float* in; float* out;
    if (N == NQ){ in = g_M + (size_t)b*NQ*WAYS;   out = g_Z + ((size_t)b*N105 + NSUP)*WAYS; }
    else        { in = g_Z + (size_t)b*N105*WAYS; out = g_Z + (size_t)b*N105*WAYS; }
    float p[J][WAYS];
    bool valid[J];
    #pragma unroll
    for (int j=0;j<J;j++){
        int r = lane + 32*j;
        valid[j] = (r < N);
        #pragma unroll
        for (int k=0;k<WAYS;k++) p[j][k] = valid[j] ? in[r*WAYS+k] : 0.0f;
    }
    int ycls = 0;
    const bool pin = (NL>0) && (lane < NL);
    if (pin) ycls = ys[b*NSUP + lane];

    if (!phaseB){
        float u[J];
        #pragma unroll
        for (int j=0;j<J;j++) u[j]=0.0f;
        int streak = 0;
        int* badp = g_bad + slot*1024;
        for (int t=0; t<MAXIT; t++){
            float rs[J]; float dvl = 0.0f;
            #pragma unroll
            for (int j=0;j<J;j++){
                rs[j] = p[j][0]+p[j][1]+p[j][2]+p[j][3]+p[j][4];
                if (valid[j]) dvl = fmaxf(dvl, fabsf(u[j]-rs[j]));
                u[j] = rs[j];
            }
            #pragma unroll
            for (int j=0;j<J;j++) if (valid[j]){
                float f = 1.0f/rs[j];
                #pragma unroll
                for (int k=0;k<WAYS;k++) p[j][k] *= f;
            }
            float cs[WAYS];
            #pragma unroll
            for (int k=0;k<WAYS;k++){
                float a = 0.0f;
                #pragma unroll
                for (int j=0;j<J;j++) if (valid[j]) a += p[j][k];
                cs[k] = a;
            }
            #pragma unroll
            for (int o=16;o;o>>=1){
                dvl = fmaxf(dvl, __shfl_xor_sync(0xffffffffu, dvl, o));
                #pragma unroll
                for (int k=0;k<WAYS;k++) cs[k] += __shfl_xor_sync(0xffffffffu, cs[k], o);
            }
            #pragma unroll
            for (int k=0;k<WAYS;k++){
                float f = cval/cs[k];
                #pragma unroll
                for (int j=0;j<J;j++) if (valid[j]) p[j][k] *= f;
            }
            if (pin){
                #pragma unroll
                for (int k=0;k<WAYS;k++) p[0][k] = (k==ycls)?1.0f:0.0f;
            }
            if (dvl > EPSV){ if (lane==0) badp[t] = 1; streak = 0; }
            else if (++streak >= 12) break;
        }
    } else {
        // per-warp scan of global bad flags: T = first t with no run bad
        const int* badp = g_bad + slot*1024;
        int myT = MAXIT;
        for (int t=lane; t<MAXIT; t+=32) if (badp[t]==0) myT = min(myT, t);
        #pragma unroll
        for (int o=16;o;o>>=1) myT = min(myT, __shfl_xor_sync(0xffffffffu, myT, o));
        const int T = myT;
        for (int t=0; t<T; t++){
            float rs[J];
            #pragma unroll
            for (int j=0;j<J;j++){
                rs[j] = p[j][0]+p[j][1]+p[j][2]+p[j][3]+p[j][4];
                if (valid[j]){
                    float f = 1.0f/rs[j];
                    #pragma unroll
                    for (int k=0;k<WAYS;k++) p[j][k] *= f;
                }
            }
            float cs[WAYS];
            #pragma unroll
            for (int k=0;k<WAYS;k++){
                float a = 0.0f;
                #pragma unroll
                for (int j=0;j<J;j++) if (valid[j]) a += p[j][k];
                cs[k] = a;
            }
            #pragma unroll
            for (int o=16;o;o>>=1){
                #pragma unroll
                for (int k=0;k<WAYS;k++) cs[k] += __shfl_xor_sync(0xffffffffu, cs[k], o);
            }
            #pragma unroll
            for (int k=0;k<WAYS;k++){
                float f = cval/cs[k];
                #pragma unroll
                for (int j=0;j<J;j++) if (valid[j]) p[j][k] *= f;
            }
            if (pin){
                #pragma unroll
                for (int k=0;k<WAYS;k++) p[0][k] = (k==ycls)?1.0f:0.0f;
            }
        }
        #pragma unroll
        for (int j=0;j<J;j++) if (valid[j]){
            int r = lane + 32*j;
            #pragma unroll
            for (int k=0;k<WAYS;k++) out[r*WAYS+k] = p[j][k];
        }
    }
}

// ---- entropy weighting, proto update, mask, write appended rows ----
__global__ void __launch_bounds__(256) k_update(const float* __restrict__ xs,
                                                const float* __restrict__ xq,
                                                const int* __restrict__ ys){
    __shared__ float z8[N100][8];
    __shared__ float ent[N100];
    __shared__ float S[WAYS];
    __shared__ float sp[WAYS*DIM];
    __shared__ float dpd[WAYS*WAYS];
    __shared__ float dpe[WAYS*WAYS];
    __shared__ float maskv[WAYS];
    __shared__ float omega_s;
    int b = blockIdx.x, tid = threadIdx.x;
    float* Zb = g_Z + (size_t)b*N105*WAYS;
    const float INVLOG5 = 0.6213349345596119f;
    if (tid < N100){
        float zv[WAYS];
        if (tid < NSUP){
            int c = ys[b*NSUP + tid];
            #pragma unroll
            for (int k=0;k<WAYS;k++) zv[k] = (k==c)?1.0f:0.0f;
        } else {
            #pragma unroll
            for (int k=0;k<WAYS;k++) zv[k] = Zb[tid*WAYS+k];
        }
        float q[WAYS]; float s = 0.0f;
        #pragma unroll
        for (int k=0;k<WAYS;k++){ q[k] = zv[k] + 1e-12f; s += q[k]; }
        float H = 0.0f;
        #pragma unroll
        for (int k=0;k<WAYS;k++){ float pp = q[k]/s; H -= pp*logf(pp); }
        float e = H*INVLOG5;
        ent[tid] = e;
        float wgt = 1.0f - e;
        #pragma unroll
        for (int k=0;k<WAYS;k++) z8[tid][k] = zv[k]*wgt;
        z8[tid][5]=0.f; z8[tid][6]=0.f; z8[tid][7]=0.f;
    }
    __syncthreads();
    if (tid < WAYS){
        float a = 0.0f;
        for (int i=0;i<N100;i++) a += z8[i][tid];
        S[tid] = a;
    }
    if (tid == 128){
        float a = 0.0f;
        for (int i=0;i<N100;i++) a += ent[i];
        omega_s = a*0.01f;
    }
    __syncthreads();
    const float* xsb = xs + (size_t)b*NSUP*DIM;
    const float* xqb = xq + (size_t)b*NQ*DIM;
    float* prb = g_proto + (size_t)b*WAYS*DIM;
    for (int d=tid; d<DIM; d+=256){
        float acc[WAYS] = {0,0,0,0,0};
        #pragma unroll 5
        for (int i=0;i<NSUP;i++){
            float f = xsb[(size_t)i*DIM + d];
            float4 zv = *(const float4*)&z8[i][0];
            float z4 = z8[i][4];
            acc[0] += zv.x*f; acc[1] += zv.y*f; acc[2] += zv.z*f;
            acc[3] += zv.w*f; acc[4] += z4*f;
        }
        #pragma unroll 5
        for (int i=0;i<NQ;i++){
            float f = xqb[(size_t)i*DIM + d];
            float4 zv = *(const float4*)&z8[NSUP+i][0];
            float z4 = z8[NSUP+i][4];
            acc[0] += zv.x*f; acc[1] += zv.y*f; acc[2] += zv.z*f;
            acc[3] += zv.w*f; acc[4] += z4*f;
        }
        #pragma unroll
        for (int k=0;k<WAYS;k++){
            float pv = 0.4f*prb[k*DIM+d] + 0.6f*(acc[k]/S[k]);
            prb[k*DIM+d] = pv;
            sp[k*DIM+d]  = pv;
        }
    }
    __syncthreads();
    int w = tid>>5, lane = tid&31;
    for (int pidx=w; pidx<WAYS*WAYS; pidx+=8){
        int a = pidx/WAYS, c = pidx%WAYS;
        float acc = 0.0f;
        for (int d=lane; d<DIM; d+=32) acc += sp[a*DIM+d]*sp[c*DIM+d];
        acc = wredSum(acc);
        if (lane==0) dpd[pidx] = acc;
    }
    __syncthreads();
    if (tid < WAYS*WAYS){
        int a = tid/WAYS, c = tid%WAYS;
        float d2 = fmaxf(dpd[a*WAYS+a] + dpd[c*WAYS+c] - 2.0f*dpd[tid], 0.0f);
        dpe[tid] = __expf(-LAMv*d2);
    }
    __syncthreads();
    if (tid < WAYS){
        float q[WAYS]; float s = 0.0f;
        #pragma unroll
        for (int k=0;k<WAYS;k++){ q[k] = dpe[tid*WAYS+k] + 1e-12f; s += q[k]; }
        float H = 0.0f;
        #pragma unroll
        for (int k=0;k<WAYS;k++){ float pp = q[k]/s; H -= pp*logf(pp); }
        maskv[tid] = (H*INVLOG5 < omega_s) ? 1.0f : 0.0f;
    }
    __syncthreads();
    float* fwr = g_ap + (size_t)b*WAYS*DIM;
    for (int t=tid; t<WAYS*DIM; t+=256) fwr[t] = sp[t]*maskv[t/DIM];
    for (int t=tid; t<N100*WAYS; t+=256) Zb[t] = z8[t/WAYS][t%WAYS];
    if (tid < WAYS*WAYS) Zb[N100*WAYS + tid] = dpe[tid]*maskv[tid/WAYS];
}

// ---- strip + cached E100 -> A=I-aW -> blocked LU solve (A X = Z) ----
__global__ void __launch_bounds__(256) k_graph_solve(const float* __restrict__ xs,
                                                     const float* __restrict__ xq){
    __shared__ float As[N105*N105];
    __shared__ float st[N105*WAYS];
    __shared__ float zz[N105*WAYS];
    __shared__ float nrm[N105];
    int b = blockIdx.x, tid = threadIdx.x;
    int w = tid>>5, lane = tid&31;
    const float* xsb = xs + (size_t)b*NSUP*DIM;
    const float* xqb = xq + (size_t)b*NQ*DIM;
    const float* apg = g_ap + (size_t)b*WAYS*DIM;

    float* ap = As;   // temp: protos in smem
    for (int t=tid; t<WAYS*DIM; t+=256) ap[t] = apg[t];
    __syncthreads();

    for (int i=w; i<N105; i+=8){
        const float* f = (i<NSUP) ? (xsb + (size_t)i*DIM)
                       : (i<N100) ? (xqb + (size_t)(i-NSUP)*DIM)
                                  : (apg + (size_t)(i-N100)*DIM);
        float nf=0.f, dk[WAYS]={0,0,0,0,0};
        for (int d=lane; d<DIM; d+=32){
            float v = f[d];
            nf += v*v;
            #pragma unroll
            for (int p=0;p<WAYS;p++) dk[p] += v*ap[p*DIM+d];
        }
        #pragma unroll
        for (int o=16;o;o>>=1){
            nf += __shfl_xor_sync(0xffffffffu, nf, o);
            #pragma unroll
            for (int p=0;p<WAYS;p++) dk[p] += __shfl_xor_sync(0xffffffffu, dk[p], o);
        }
        if (lane==0){
            nrm[i] = nf;
            #pragma unroll
            for (int p=0;p<WAYS;p++) st[i*WAYS+p] = dk[p];
        }
    }
    __syncthreads();

    const float* E = g_E100 + (size_t)b*N100*N100;
    for (int t=tid; t<N105*N105; t+=256){
        int i = t/N105, j = t - i*N105;
        float v;
        if (i < N100 && j < N100){
            v = E[i*N100+j];
        } else if (i == j){
            v = 0.0f;
        } else {
            float dot = (j >= N100) ? st[i*WAYS + (j-N100)] : st[j*WAYS + (i-N100)];
            float d2 = fmaxf(nrm[i] + nrm[j] - 2.0f*dot, 0.0f);
            v = __expf(-LAMv*d2);
        }
        As[t] = v;
    }
    float* Zb = g_Z + (size_t)b*N105*WAYS;
    for (int t=tid; t<N105*WAYS; t+=256) zz[t] = Zb[t];
    __syncthreads();

    if (tid < N105){
        float s = 0.0f;
        for (int j=0;j<N105;j++) s += As[tid*N105+j];
        nrm[tid] = rsqrtf(s);
    }
    __syncthreads();
    for (int t=tid; t<N105*N105; t+=256){
        int i = t/N105, j = t - i*N105;
        As[t] = ((i==j)?1.0f:0.0f) - 0.7f*nrm[i]*nrm[j]*As[t];
    }
    __syncthreads();

    // ---- rank-4 blocked LU forward elimination (SPD, no pivoting) ----
    for (int K=0; K<26; K++){
        const int k0 = 4*K;
        // panel factor (warp 0)
        if (w==0){
            #pragma unroll
            for (int kk=0; kk<4; kk++){
                int pc = k0+kk;
                float inv = 1.0f/As[pc*N105+pc];
                for (int i=pc+1+lane; i<N105; i+=32){
                    float l = As[i*N105+pc]*inv;
                    As[i*N105+pc] = l;
                    #pragma unroll
                    for (int c=kk+1; c<4; c++)
                        As[i*N105+k0+c] -= l*As[pc*N105+k0+c];
                }
                __syncwarp();
            }
        }
        __syncthreads();
        // apply L_panel^{-1} to pivot rows' trailing cols + zz rows
        float l10=As[(k0+1)*N105+k0];
        float l20=As[(k0+2)*N105+k0], l21=As[(k0+2)*N105+k0+1];
        float l30=As[(k0+3)*N105+k0], l31=As[(k0+3)*N105+k0+1], l32=As[(k0+3)*N105+k0+2];
        for (int j=k0+4+tid; j<N105; j+=256){
            float a0=As[(k0+0)*N105+j], a1=As[(k0+1)*N105+j];
            float a2=As[(k0+2)*N105+j], a3=As[(k0+3)*N105+j];
            a1 -= l10*a0;
            a2 -= l20*a0 + l21*a1;
            a3 -= l30*a0 + l31*a1 + l32*a2;
            As[(k0+1)*N105+j]=a1; As[(k0+2)*N105+j]=a2; As[(k0+3)*N105+j]=a3;
        }
        if (tid < WAYS){
            float a0=zz[(k0+0)*WAYS+tid], a1=zz[(k0+1)*WAYS+tid];
            float a2=zz[(k0+2)*WAYS+tid], a3=zz[(k0+3)*WAYS+tid];
            a1 -= l10*a0;
            a2 -= l20*a0 + l21*a1;
            a3 -= l30*a0 + l31*a1 + l32*a2;
            zz[(k0+1)*WAYS+tid]=a1; zz[(k0+2)*WAYS+tid]=a2; zz[(k0+3)*WAYS+tid]=a3;
        }
        __syncthreads();
        // trailing rank-4 update
        const int j0 = k0+4+lane;
        float u0[4], u1[4], u2[4], u3[4], uz0,uz1,uz2,uz3;
        #pragma unroll
        for (int e=0;e<4;e++){
            int j = j0+32*e;
            bool ok = (j<N105);
            u0[e] = ok ? As[(k0+0)*N105+j] : 0.0f;
            u1[e] = ok ? As[(k0+1)*N105+j] : 0.0f;
            u2[e] = ok ? As[(k0+2)*N105+j] : 0.0f;
            u3[e] = ok ? As[(k0+3)*N105+j] : 0.0f;
        }
        uz0 = (lane<WAYS)? zz[(k0+0)*WAYS+lane] : 0.0f;
        uz1 = (lane<WAYS)? zz[(k0+1)*WAYS+lane] : 0.0f;
        uz2 = (lane<WAYS)? zz[(k0+2)*WAYS+lane] : 0.0f;
        uz3 = (lane<WAYS)? zz[(k0+3)*WAYS+lane] : 0.0f;
        for (int i=k0+4+w; i<N105; i+=8){
            float l0=As[i*N105+k0+0], l1=As[i*N105+k0+1];
            float l2=As[i*N105+k0+2], l3=As[i*N105+k0+3];
            #pragma unroll
            for (int e=0;e<4;e++){
                int j = j0+32*e;
                if (j<N105)
                    As[i*N105+j] -= l0*u0[e]+l1*u1[e]+l2*u2[e]+l3*u3[e];
            }
            if (lane<WAYS)
                zz[i*WAYS+lane] -= l0*uz0+l1*uz1+l2*uz2+l3*uz3;
        }
        __syncthreads();
    }

    // ---- blocked back substitution ----
    if (tid < WAYS) zz[104*WAYS+tid] /= As[104*N105+104];
    __syncthreads();
    for (int t=tid; t<104*WAYS; t+=256){
        int i=t/WAYS, m=t-i*WAYS;
        zz[t] -= As[i*N105+104]*zz[104*WAYS+m];
    }
    __syncthreads();
    for (int K=25; K>=0; K--){
        const int lo = 4*K, hi = lo+3;
        if (w==0 && lane<WAYS){
            for (int r=hi; r>=lo; r--){
                float acc = zz[r*WAYS+lane];
                for (int c=r+1; c<=hi; c++) acc -= As[r*N105+c]*zz[c*WAYS+lane];
                zz[r*WAYS+lane] = acc / As[r*N105+r];
            }
        }
        __syncthreads();
        if (lo > 0){
            float x0[WAYS];
            #pragma unroll
            for (int m=0;m<WAYS;m++) x0[m] = 0.0f;  // unused placeholder
            for (int t=tid; t<lo*WAYS; t+=256){
                int i=t/WAYS, m=t-i*WAYS;
                float s = As[i*N105+lo+0]*zz[(lo+0)*WAYS+m]
                        + As[i*N105+lo+1]*zz[(lo+1)*WAYS+m]
                        + As[i*N105+lo+2]*zz[(lo+2)*WAYS+m]
                        + As[i*N105+lo+3]*zz[(lo+3)*WAYS+m];
                zz[t] -= s;
            }
        }
        __syncthreads();
    }
    for (int t=tid; t<N105*WAYS; t+=256) Zb[t] = zz[t];
}

// ---- accuracy over queries ----
__global__ void __launch_bounds__(128) k_acc(const int* __restrict__ yq, float* __restrict__ out){
    __shared__ int cnt[128];
    int b = blockIdx.x, tid = threadIdx.x;
    int m = 0;
    if (tid < NQ){
        const float* zr = g_Z + ((size_t)b*N105 + NSUP + tid)*WAYS;
        float best = zr[0]; int bi = 0;
        #pragma unroll
        for (int k=1;k<WAYS;k++){ if (zr[k] > best){ best = zr[k]; bi = k; } }
        m = (bi == yq[b*NQ + tid]) ? 1 : 0;
    }
    cnt[tid] = m;
    __syncthreads();
    for (int s=64; s; s>>=1){ if (tid < s) cnt[tid] += cnt[tid+s]; __syncthreads(); }
    if (tid==0) out[b] = (float)cnt[0] / 75.0f;
}

extern "C" void kernel_launch(void* const* d_in, const int* in_sizes, int n_in,
                              void* d_out, int out_size){
    const float* xs = (const float*)d_in[0];
    const float* xq = (const float*)d_in[1];
    const int*   ys = (const int*)d_in[2];
    const int*   yq = (const int*)d_in[3];
    float* out = (float*)d_out;
    (void)in_sizes; (void)n_in; (void)out_size;

    k_init<<<RUNS,256>>>(xs);                                  // 0
    // epoch 0 (gram0 deferred to launch index 5 for ncu visibility)
    k_dist_proto<<<RUNS,256>>>(xq);                            // 1
    k_sinkhorn<NQ,0><<<64,256>>>(ys, 0, 0);                    // 2
    k_sinkhorn<NQ,0><<<64,256>>>(ys, 0, 1);                    // 3
    k_update<<<RUNS,256>>>(xs, xq, ys);                        // 4
    k_gram0<<<RUNS,256>>>(xs, xq);                             // 5  <- profiled
    k_graph_solve<<<RUNS,256>>>(xs, xq);                       // 6
    k_sinkhorn<N105,NSUP><<<64,256>>>(ys, 1, 0);               // 7
    k_sinkhorn<N105,NSUP><<<64,256>>>(ys, 1, 1);               // 8
    for (int e=1;e<3;e++){
        k_dist_proto<<<RUNS,256>>>(xq);
        k_sinkhorn<NQ,0><<<64,256>>>(ys, 2*e, 0);
        k_sinkhorn<NQ,0><<<64,256>>>(ys, 2*e, 1);
        k_update<<<RUNS,256>>>(xs, xq, ys);
        k_graph_solve<<<RUNS,256>>>(xs, xq);
        k_sinkhorn<N105,NSUP><<<64,256>>>(ys, 2*e+1, 0);
        k_sinkhorn<N105,NSUP><<<64,256>>>(ys, 2*e+1, 1);
    }
    k_acc<<<RUNS,128>>>(yq, out);
}

// round 12
// speedup vs baseline: 1.8938x; 1.4632x over previous
#include <cuda_runtime.h>
#include <math.h>

#define RUNS 512
#define WAYS 5
#define SHOT 5
#define NSUP 25
#define NQ   75
#define N100 100
#define N105 105
#define DIM  640
#define LAMv 10.0f
#define EPSV 0.001f
#define MAXIT 1000
#define TPW 130

typedef unsigned long long u64t;
__device__ __forceinline__ u64t pk2(float lo, float hi){
    u64t r; asm("mov.b64 %0,{%1,%2};" : "=l"(r) : "f"(lo), "f"(hi)); return r;
}
__device__ __forceinline__ float2 upk2(u64t v){
    float2 r; asm("mov.b64 {%0,%1},%2;" : "=f"(r.x), "=f"(r.y) : "l"(v)); return r;
}
__device__ __forceinline__ void ffma2(u64t &acc, u64t a, u64t b){
    asm("fma.rn.f32x2 %0,%1,%2,%0;" : "+l"(acc) : "l"(a), "l"(b));
}

__device__ float g_ap[(size_t)RUNS*WAYS*DIM];
__device__ float g_proto[(size_t)RUNS*WAYS*DIM];
__device__ float g_M[(size_t)RUNS*NQ*WAYS];
__device__ float g_Z[(size_t)RUNS*N105*WAYS];
__device__ float g_E100[(size_t)RUNS*N100*N100];
__device__ int   g_bad[4*1024];

__device__ __forceinline__ float wredSum(float v){
    #pragma unroll
    for (int o=16;o;o>>=1) v += __shfl_xor_sync(0xffffffffu, v, o);
    return v;
}

// ================= sinkhorn device routines (warp-collective) =============
template<int N, int NL>
__device__ __forceinline__ void sink_phaseA(const float* __restrict__ in,
                                            const int* __restrict__ ysb,
                                            int* __restrict__ badp, int lane){
    constexpr int J = (N+31)/32;
    const float cval = (float)(N/WAYS);
    float p[J][WAYS]; bool valid[J];
    #pragma unroll
    for (int j=0;j<J;j++){
        int r = lane+32*j; valid[j] = (r<N);
        #pragma unroll
        for (int k=0;k<WAYS;k++) p[j][k] = valid[j] ? in[r*WAYS+k] : 0.0f;
    }
    int ycls = 0;
    const bool pin = (NL>0) && (lane < NL);
    if (pin) ycls = ysb[lane];
    float u[J];
    #pragma unroll
    for (int j=0;j<J;j++) u[j]=0.0f;
    int streak = 0;
    for (int t=0; t<MAXIT; t++){
        float rs[J]; float dvl = 0.0f;
        #pragma unroll
        for (int j=0;j<J;j++){
            rs[j] = p[j][0]+p[j][1]+p[j][2]+p[j][3]+p[j][4];
            if (valid[j]) dvl = fmaxf(dvl, fabsf(u[j]-rs[j]));
            u[j] = rs[j];
        }
        #pragma unroll
        for (int j=0;j<J;j++) if (valid[j]){
            float f = 1.0f/rs[j];
            #pragma unroll
            for (int k=0;k<WAYS;k++) p[j][k] *= f;
        }
        float cs[WAYS];
        #pragma unroll
        for (int k=0;k<WAYS;k++){
            float a = 0.0f;
            #pragma unroll
            for (int j=0;j<J;j++) if (valid[j]) a += p[j][k];
            cs[k] = a;
        }
        #pragma unroll
        for (int o=16;o;o>>=1){
            dvl = fmaxf(dvl, __shfl_xor_sync(0xffffffffu, dvl, o));
            #pragma unroll
            for (int k=0;k<WAYS;k++) cs[k] += __shfl_xor_sync(0xffffffffu, cs[k], o);
        }
        #pragma unroll
        for (int k=0;k<WAYS;k++){
            float f = cval/cs[k];
            #pragma unroll
            for (int j=0;j<J;j++) if (valid[j]) p[j][k] *= f;
        }
        if (pin){
            #pragma unroll
            for (int k=0;k<WAYS;k++) p[0][k] = (k==ycls)?1.0f:0.0f;
        }
        if (dvl > EPSV){ if (lane==0) badp[t] = 1; streak = 0; }
        else if (++streak >= 12) break;
    }
}

template<int N, int NL>
__device__ __forceinline__ void sink_phaseB(const float* __restrict__ in,
                                            const int* __restrict__ ysb,
                                            const int* __restrict__ badp, int lane,
                                            float (&p)[(N+31)/32][WAYS]){
    constexpr int J = (N+31)/32;
    const float cval = (float)(N/WAYS);
    bool valid[J];
    #pragma unroll
    for (int j=0;j<J;j++){
        int r = lane+32*j; valid[j] = (r<N);
        #pragma unroll
        for (int k=0;k<WAYS;k++) p[j][k] = valid[j] ? in[r*WAYS+k] : 0.0f;
    }
    int ycls = 0;
    const bool pin = (NL>0) && (lane < NL);
    if (pin) ycls = ysb[lane];
    int myT = MAXIT;
    for (int t=lane; t<MAXIT; t+=32) if (badp[t]==0) myT = min(myT, t);
    #pragma unroll
    for (int o=16;o;o>>=1) myT = min(myT, __shfl_xor_sync(0xffffffffu, myT, o));
    const int T = myT;
    for (int t=0; t<T; t++){
        float rs[J];
        #pragma unroll
        for (int j=0;j<J;j++){
            rs[j] = p[j][0]+p[j][1]+p[j][2]+p[j][3]+p[j][4];
            if (valid[j]){
                float f = 1.0f/rs[j];
                #pragma unroll
                for (int k=0;k<WAYS;k++) p[j][k] *= f;
            }
        }
        float cs[WAYS];
        #pragma unroll
        for (int k=0;k<WAYS;k++){
            float a = 0.0f;
            #pragma unroll
            for (int j=0;j<J;j++) if (valid[j]) a += p[j][k];
            cs[k] = a;
        }
        #pragma unroll
        for (int o=16;o;o>>=1){
            #pragma unroll
            for (int k=0;k<WAYS;k++) cs[k] += __shfl_xor_sync(0xffffffffu, cs[k], o);
        }
        #pragma unroll
        for (int k=0;k<WAYS;k++){
            float f = cval/cs[k];
            #pragma unroll
            for (int j=0;j<J;j++) if (valid[j]) p[j][k] *= f;
        }
        if (pin){
            #pragma unroll
            for (int k=0;k<WAYS;k++) p[0][k] = (k==ycls)?1.0f:0.0f;
        }
    }
}

// ================= K: zero bad flags ======================================
__global__ void k_zero(){
    int tid = threadIdx.x;
    for (int t=tid; t<4*1024; t+=256) g_bad[t]=0;
}

// ================= K: proto init + dist(e0) + sinkA75(slot0) ==============
__global__ void __launch_bounds__(256) k_front(const float* __restrict__ xs,
                                               const float* __restrict__ xq){
    __shared__ float sp[WAYS*DIM];
    __shared__ float pn[WAYS];
    __shared__ float Msm[NQ*WAYS];
    int b = blockIdx.x, tid = threadIdx.x;
    int w = tid>>5, lane = tid&31;
    const float* s0 = xs + (size_t)b*NSUP*DIM;
    float* pr = g_proto + (size_t)b*WAYS*DIM;
    for (int t=tid; t<WAYS*DIM; t+=256){
        int ww = t/DIM, d = t-ww*DIM;
        float a = 0.f;
        #pragma unroll
        for (int s=0;s<SHOT;s++) a += s0[(ww*SHOT+s)*DIM + d];
        float v = a*0.2f;
        sp[t] = v; pr[t] = v;
    }
    __syncthreads();
    if (w < WAYS){
        float a=0.f;
        for (int d=lane; d<DIM; d+=32){ float v=sp[w*DIM+d]; a += v*v; }
        a = wredSum(a);
        if (lane==0) pn[w]=a;
    }
    __syncthreads();
    const float* xqb = xq + (size_t)b*NQ*DIM;
    for (int r=w; r<NQ; r+=8){
        const float* f = xqb + (size_t)r*DIM;
        float nf=0.f, dk[WAYS]={0,0,0,0,0};
        for (int d=lane; d<DIM; d+=32){
            float v = f[d];
            nf += v*v;
            #pragma unroll
            for (int k=0;k<WAYS;k++) dk[k] += v*sp[k*DIM+d];
        }
        #pragma unroll
        for (int o=16;o;o>>=1){
            nf += __shfl_xor_sync(0xffffffffu, nf, o);
            #pragma unroll
            for (int k=0;k<WAYS;k++) dk[k] += __shfl_xor_sync(0xffffffffu, dk[k], o);
        }
        if (lane < WAYS){
            float d2 = fmaxf(nf + pn[lane] - 2.0f*dk[lane], 0.0f);
            float m = __expf(-LAMv*d2);
            Msm[r*WAYS+lane] = m;
            g_M[((size_t)b*NQ + r)*WAYS + lane] = m;
        }
    }
    __syncthreads();
    if (w==0) sink_phaseA<NQ,0>(Msm, (const int*)0, g_bad + 0*1024, lane);
}

// ===== K: sinkB75(slot_in) + update (+dist + sinkA75(slot_out) if !full) ===
__global__ void __launch_bounds__(256) k_mid(const float* __restrict__ xs,
                                             const float* __restrict__ xq,
                                             const int* __restrict__ ys,
                                             int slot_in, int slot_out, int full){
    __shared__ __align__(16) float z8[N100][8];
    __shared__ float zq[376];           // NQ*WAYS=375 used, padded
    __shared__ float entm[N100];
    __shared__ float S[WAYS];
    __shared__ float sp[WAYS*DIM];
    __shared__ float pn[WAYS];
    __shared__ float Msm[NQ*WAYS];
    __shared__ float dpd[WAYS*WAYS];
    __shared__ float dpe[WAYS*WAYS];
    __shared__ float maskv[WAYS];
    __shared__ float omega_s;
    int b = blockIdx.x, tid = threadIdx.x;
    int w = tid>>5, lane = tid&31;
    const float INVLOG5 = 0.6213349345596119f;

    if (w==0){
        float p[(NQ+31)/32][WAYS];
        sink_phaseB<NQ,0>(g_M + (size_t)b*NQ*WAYS, (const int*)0,
                          g_bad + slot_in*1024, lane, p);
        #pragma unroll
        for (int j=0;j<(NQ+31)/32;j++){
            int r = lane+32*j;
            if (r<NQ){
                #pragma unroll
                for (int k=0;k<WAYS;k++) zq[r*WAYS+k] = p[j][k];
            }
        }
    }
    __syncthreads();

    if (tid < N100){
        float zv[WAYS];
        if (tid < NSUP){
            int c = ys[b*NSUP + tid];
            #pragma unroll
            for (int k=0;k<WAYS;k++) zv[k] = (k==c)?1.0f:0.0f;
        } else {
            #pragma unroll
            for (int k=0;k<WAYS;k++) zv[k] = zq[(tid-NSUP)*WAYS+k];
        }
        float q[WAYS]; float s = 0.0f;
        #pragma unroll
        for (int k=0;k<WAYS;k++){ q[k] = zv[k] + 1e-12f; s += q[k]; }
        float H = 0.0f;
        #pragma unroll
        for (int k=0;k<WAYS;k++){ float pp = q[k]/s; H -= pp*logf(pp); }
        float e = H*INVLOG5;
        entm[tid] = e;
        float wgt = 1.0f - e;
        #pragma unroll
        for (int k=0;k<WAYS;k++) z8[tid][k] = zv[k]*wgt;
        z8[tid][5]=0.f; z8[tid][6]=0.f; z8[tid][7]=0.f;
    }
    __syncthreads();
    if (tid < WAYS){
        float a = 0.0f;
        for (int i=0;i<N100;i++) a += z8[i][tid];
        S[tid] = a;
    }
    if (tid == 128){
        float a = 0.0f;
        for (int i=0;i<N100;i++) a += entm[i];
        omega_s = a*0.01f;
    }
    __syncthreads();
    const float* xsb = xs + (size_t)b*NSUP*DIM;
    const float* xqb = xq + (size_t)b*NQ*DIM;
    float* prb = g_proto + (size_t)b*WAYS*DIM;
    for (int d=tid; d<DIM; d+=256){
        float acc[WAYS] = {0,0,0,0,0};
        #pragma unroll 5
        for (int i=0;i<NSUP;i++){
            float f = xsb[(size_t)i*DIM + d];
            float4 zv = *(const float4*)&z8[i][0];
            float z4 = z8[i][4];
            acc[0] += zv.x*f; acc[1] += zv.y*f; acc[2] += zv.z*f;
            acc[3] += zv.w*f; acc[4] += z4*f;
        }
        #pragma unroll 5
        for (int i=0;i<NQ;i++){
            float f = xqb[(size_t)i*DIM + d];
            float4 zv = *(const float4*)&z8[NSUP+i][0];
            float z4 = z8[NSUP+i][4];
            acc[0] += zv.x*f; acc[1] += zv.y*f; acc[2] += zv.z*f;
            acc[3] += zv.w*f; acc[4] += z4*f;
        }
        #pragma unroll
        for (int k=0;k<WAYS;k++){
            float pv = 0.4f*prb[k*DIM+d] + 0.6f*(acc[k]/S[k]);
            prb[k*DIM+d] = pv;
            sp[k*DIM+d]  = pv;
        }
    }
    __syncthreads();

    if (full){
        for (int pidx=w; pidx<WAYS*WAYS; pidx+=8){
            int a = pidx/WAYS, c = pidx%WAYS;
            float acc = 0.0f;
            for (int d=lane; d<DIM; d+=32) acc += sp[a*DIM+d]*sp[c*DIM+d];
            acc = wredSum(acc);
            if (lane==0) dpd[pidx] = acc;
        }
        __syncthreads();
        if (tid < WAYS*WAYS){
            int a = tid/WAYS, c = tid%WAYS;
            float d2 = fmaxf(dpd[a*WAYS+a] + dpd[c*WAYS+c] - 2.0f*dpd[tid], 0.0f);
            dpe[tid] = __expf(-LAMv*d2);
        }
        __syncthreads();
        if (tid < WAYS){
            float q[WAYS]; float s = 0.0f;
            #pragma unroll
            for (int k=0;k<WAYS;k++){ q[k] = dpe[tid*WAYS+k] + 1e-12f; s += q[k]; }
            float H = 0.0f;
            #pragma unroll
            for (int k=0;k<WAYS;k++){ float pp = q[k]/s; H -= pp*logf(pp); }
            maskv[tid] = (H*INVLOG5 < omega_s) ? 1.0f : 0.0f;
        }
        __syncthreads();
        float* Zb = g_Z + (size_t)b*N105*WAYS;
        float* fwr = g_ap + (size_t)b*WAYS*DIM;
        for (int t=tid; t<WAYS*DIM; t+=256) fwr[t] = sp[t]*maskv[t/DIM];
        for (int t=tid; t<N100*WAYS; t+=256) Zb[t] = z8[t/WAYS][t%WAYS];
        if (tid < WAYS*WAYS) Zb[N100*WAYS + tid] = dpe[tid]*maskv[tid/WAYS];
        return;
    }

    // dist for next epoch + sinkA
    if (w < WAYS){
        float a=0.f;
        for (int d=lane; d<DIM; d+=32){ float v=sp[w*DIM+d]; a += v*v; }
        a = wredSum(a);
        if (lane==0) pn[w]=a;
    }
    __syncthreads();
    for (int r=w; r<NQ; r+=8){
        const float* f = xqb + (size_t)r*DIM;
        float nf=0.f, dk[WAYS]={0,0,0,0,0};
        for (int d=lane; d<DIM; d+=32){
            float v = f[d];
            nf += v*v;
            #pragma unroll
            for (int k=0;k<WAYS;k++) dk[k] += v*sp[k*DIM+d];
        }
        #pragma unroll
        for (int o=16;o;o>>=1){
            nf += __shfl_xor_sync(0xffffffffu, nf, o);
            #pragma unroll
            for (int k=0;k<WAYS;k++) dk[k] += __shfl_xor_sync(0xffffffffu, dk[k], o);
        }
        if (lane < WAYS){
            float d2 = fmaxf(nf + pn[lane] - 2.0f*dk[lane], 0.0f);
            float m = __expf(-LAMv*d2);
            Msm[r*WAYS+lane] = m;
            g_M[((size_t)b*NQ + r)*WAYS + lane] = m;
        }
    }
    __syncthreads();
    if (w==0) sink_phaseA<NQ,0>(Msm, (const int*)0, g_bad + slot_out*1024, lane);
}

// ================= one-time 100x100 exp(-lam*d2) cache (FFMA2) ============
__global__ void __launch_bounds__(256) k_gram0(const float* __restrict__ xs,
                                               const float* __restrict__ xq){
    __shared__ float tile[64*TPW];
    __shared__ float nd[128];
    int b = blockIdx.x, tid = threadIdx.x;
    int tx = tid & 15, ty = tid >> 4;
    u64t acc2[7][4];
    #pragma unroll
    for (int i=0;i<7;i++)
        #pragma unroll
        for (int e=0;e<4;e++) acc2[i][e] = pk2(0.f,0.f);
    for (int t=tid; t<64*TPW; t+=256) tile[t]=0.f;
    __syncthreads();
    const float* xsb = xs + (size_t)b*NSUP*DIM;
    const float* xqb = xq + (size_t)b*NQ*DIM;
    for (int c=0;c<10;c++){
        for (int t=tid; t<N100*64; t+=256){
            int row = t>>6, k = t&63;
            const float* fr = (row<NSUP) ? (xsb + (size_t)row*DIM)
                                         : (xqb + (size_t)(row-NSUP)*DIM);
            tile[k*TPW+row] = fr[c*64+k];
        }
        __syncthreads();
        #pragma unroll 2
        for (int k=0;k<64;k++){
            const float* tk = &tile[k*TPW];
            u64t ap[7], bp[4];
            #pragma unroll
            for (int i=0;i<7;i++){ float a = tk[ty+16*i]; ap[i]=pk2(a,a); }
            #pragma unroll
            for (int e=0;e<4;e++){
                float2 bv = *(const float2*)(tk + 2*tx + 32*e);
                bp[e] = pk2(bv.x, bv.y);
            }
            #pragma unroll
            for (int i=0;i<7;i++)
                #pragma unroll
                for (int e=0;e<4;e++) ffma2(acc2[i][e], ap[i], bp[e]);
        }
        __syncthreads();
    }
    #pragma unroll
    for (int i=0;i<7;i++){
        int r = ty+16*i;
        #pragma unroll
        for (int e=0;e<4;e++){
            int c = 2*tx+32*e;
            if (c==r || c+1==r){
                float2 g = upk2(acc2[i][e]);
                if (c==r)   nd[r] = g.x;
                if (c+1==r) nd[r] = g.y;
            }
        }
    }
    __syncthreads();
    float* E = g_E100 + (size_t)b*N100*N100;
    #pragma unroll
    for (int i=0;i<7;i++){
        int r = ty+16*i;
        if (r < N100){
            float nr = nd[r];
            #pragma unroll
            for (int e=0;e<4;e++){
                int c = 2*tx+32*e;
                float2 g = upk2(acc2[i][e]);
                if (c < N100){
                    float d2 = fmaxf(nr+nd[c]-2.0f*g.x, 0.0f);
                    E[r*N100+c] = (r==c)?0.0f:__expf(-LAMv*d2);
                }
                if (c+1 < N100){
                    float d2 = fmaxf(nr+nd[c+1]-2.0f*g.y, 0.0f);
                    E[r*N100+c+1] = (r==c+1)?0.0f:__expf(-LAMv*d2);
                }
            }
        }
    }
}

// ====== K: strip + E100 -> A=I-aW -> blocked LU solve + sinkA105(slot3) ====
__global__ void __launch_bounds__(256) k_solve(const float* __restrict__ xs,
                                               const float* __restrict__ xq,
                                               const int* __restrict__ ys){
    __shared__ float As[N105*N105];
    __shared__ float st[N105*WAYS];
    __shared__ float zz[N105*WAYS];
    __shared__ float nrm[N105];
    int b = blockIdx.x, tid = threadIdx.x;
    int w = tid>>5, lane = tid&31;
    const float* xsb = xs + (size_t)b*NSUP*DIM;
    const float* xqb = xq + (size_t)b*NQ*DIM;
    const float* apg = g_ap + (size_t)b*WAYS*DIM;

    float* ap = As;
    for (int t=tid; t<WAYS*DIM; t+=256) ap[t] = apg[t];
    __syncthreads();

    for (int i=w; i<N105; i+=8){
        const float* f = (i<NSUP) ? (xsb + (size_t)i*DIM)
                       : (i<N100) ? (xqb + (size_t)(i-NSUP)*DIM)
                                  : (apg + (size_t)(i-N100)*DIM);
        float nf=0.f, dk[WAYS]={0,0,0,0,0};
        for (int d=lane; d<DIM; d+=32){
            float v = f[d];
            nf += v*v;
            #pragma unroll
            for (int p=0;p<WAYS;p++) dk[p] += v*ap[p*DIM+d];
        }
        #pragma unroll
        for (int o=16;o;o>>=1){
            nf += __shfl_xor_sync(0xffffffffu, nf, o);
            #pragma unroll
            for (int p=0;p<WAYS;p++) dk[p] += __shfl_xor_sync(0xffffffffu, dk[p], o);
        }
        if (lane==0){
            nrm[i] = nf;
            #pragma unroll
            for (int p=0;p<WAYS;p++) st[i*WAYS+p] = dk[p];
        }
    }
    __syncthreads();

    const float* E = g_E100 + (size_t)b*N100*N100;
    for (int t=tid; t<N105*N105; t+=256){
        int i = t/N105, j = t - i*N105;
        float v;
        if (i < N100 && j < N100){
            v = E[i*N100+j];
        } else if (i == j){
            v = 0.0f;
        } else {
            float dot = (j >= N100) ? st[i*WAYS + (j-N100)] : st[j*WAYS + (i-N100)];
            float d2 = fmaxf(nrm[i] + nrm[j] - 2.0f*dot, 0.0f);
            v = __expf(-LAMv*d2);
        }
        As[t] = v;
    }
    float* Zb = g_Z + (size_t)b*N105*WAYS;
    for (int t=tid; t<N105*WAYS; t+=256) zz[t] = Zb[t];
    __syncthreads();

    if (tid < N105){
        float s = 0.0f;
        for (int j=0;j<N105;j++) s += As[tid*N105+j];
        nrm[tid] = rsqrtf(s);
    }
    __syncthreads();
    for (int t=tid; t<N105*N105; t+=256){
        int i = t/N105, j = t - i*N105;
        As[t] = ((i==j)?1.0f:0.0f) - 0.7f*nrm[i]*nrm[j]*As[t];
    }
    __syncthreads();

    for (int K=0; K<26; K++){
        const int k0 = 4*K;
        if (w==0){
            #pragma unroll
            for (int kk=0; kk<4; kk++){
                int pc = k0+kk;
                float inv = 1.0f/As[pc*N105+pc];
                for (int i=pc+1+lane; i<N105; i+=32){
                    float l = As[i*N105+pc]*inv;
                    As[i*N105+pc] = l;
                    #pragma unroll
                    for (int c=kk+1; c<4; c++)
                        As[i*N105+k0+c] -= l*As[pc*N105+k0+c];
                }
                __syncwarp();
            }
        }
        __syncthreads();
        float l10=As[(k0+1)*N105+k0];
        float l20=As[(k0+2)*N105+k0], l21=As[(k0+2)*N105+k0+1];
        float l30=As[(k0+3)*N105+k0], l31=As[(k0+3)*N105+k0+1], l32=As[(k0+3)*N105+k0+2];
        for (int j=k0+4+tid; j<N105; j+=256){
            float a0=As[(k0+0)*N105+j], a1=As[(k0+1)*N105+j];
            float a2=As[(k0+2)*N105+j], a3=As[(k0+3)*N105+j];
            a1 -= l10*a0;
            a2 -= l20*a0 + l21*a1;
            a3 -= l30*a0 + l31*a1 + l32*a2;
            As[(k0+1)*N105+j]=a1; As[(k0+2)*N105+j]=a2; As[(k0+3)*N105+j]=a3;
        }
        if (tid < WAYS){
            float a0=zz[(k0+0)*WAYS+tid], a1=zz[(k0+1)*WAYS+tid];
            float a2=zz[(k0+2)*WAYS+tid], a3=zz[(k0+3)*WAYS+tid];
            a1 -= l10*a0;
            a2 -= l20*a0 + l21*a1;
            a3 -= l30*a0 + l31*a1 + l32*a2;
            zz[(k0+1)*WAYS+tid]=a1; zz[(k0+2)*WAYS+tid]=a2; zz[(k0+3)*WAYS+tid]=a3;
        }
        __syncthreads();
        const int j0 = k0+4+lane;
        float u0[4], u1[4], u2[4], u3[4], uz0,uz1,uz2,uz3;
        #pragma unroll
        for (int e=0;e<4;e++){
            int j = j0+32*e;
            bool ok = (j<N105);
            u0[e] = ok ? As[(k0+0)*N105+j] : 0.0f;
            u1[e] = ok ? As[(k0+1)*N105+j] : 0.0f;
            u2[e] = ok ? As[(k0+2)*N105+j] : 0.0f;
            u3[e] = ok ? As[(k0+3)*N105+j] : 0.0f;
        }
        uz0 = (lane<WAYS)? zz[(k0+0)*WAYS+lane] : 0.0f;
        uz1 = (lane<WAYS)? zz[(k0+1)*WAYS+lane] : 0.0f;
        uz2 = (lane<WAYS)? zz[(k0+2)*WAYS+lane] : 0.0f;
        uz3 = (lane<WAYS)? zz[(k0+3)*WAYS+lane] : 0.0f;
        for (int i=k0+4+w; i<N105; i+=8){
            float l0=As[i*N105+k0+0], l1=As[i*N105+k0+1];
            float l2=As[i*N105+k0+2], l3=As[i*N105+k0+3];
            #pragma unroll
            for (int e=0;e<4;e++){
                int j = j0+32*e;
                if (j<N105)
                    As[i*N105+j] -= l0*u0[e]+l1*u1[e]+l2*u2[e]+l3*u3[e];
            }
            if (lane<WAYS)
                zz[i*WAYS+lane] -= l0*uz0+l1*uz1+l2*uz2+l3*uz3;
        }
        __syncthreads();
    }

    if (tid < WAYS) zz[104*WAYS+tid] /= As[104*N105+104];
    __syncthreads();
    for (int t=tid; t<104*WAYS; t+=256){
        int i=t/WAYS, m=t-i*WAYS;
        zz[t] -= As[i*N105+104]*zz[104*WAYS+m];
    }
    __syncthreads();
    for (int K=25; K>=0; K--){
        const int lo = 4*K, hi = lo+3;
        if (w==0 && lane<WAYS){
            for (int r=hi; r>=lo; r--){
                float acc = zz[r*WAYS+lane];
                for (int c=r+1; c<=hi; c++) acc -= As[r*N105+c]*zz[c*WAYS+lane];
                zz[r*WAYS+lane] = acc / As[r*N105+r];
            }
        }
        __syncthreads();
        if (lo > 0){
            for (int t=tid; t<lo*WAYS; t+=256){
                int i=t/WAYS, m=t-i*WAYS;
                float s = As[i*N105+lo+0]*zz[(lo+0)*WAYS+m]
                        + As[i*N105+lo+1]*zz[(lo+1)*WAYS+m]
                        + As[i*N105+lo+2]*zz[(lo+2)*WAYS+m]
                        + As[i*N105+lo+3]*zz[(lo+3)*WAYS+m];
                zz[t] -= s;
            }
        }
        __syncthreads();
    }
    for (int t=tid; t<N105*WAYS; t+=256) Zb[t] = zz[t];
    __syncthreads();
    if (w==0) sink_phaseA<N105,NSUP>(zz, ys + b*NSUP, g_bad + 3*1024, lane);
}

// ================= K: sinkB105(slot3) + accuracy ==========================
__global__ void __launch_bounds__(128) k_final(const int* __restrict__ ys,
                                               const int* __restrict__ yq,
                                               float* __restrict__ out){
    int gw = blockIdx.x*4 + (threadIdx.x>>5);
    int lane = threadIdx.x & 31;
    if (gw >= RUNS) return;
    int b = gw;
    float p[(N105+31)/32][WAYS];
    sink_phaseB<N105,NSUP>(g_Z + (size_t)b*N105*WAYS, ys + b*NSUP,
                           g_bad + 3*1024, lane, p);
    int cnt = 0;
    #pragma unroll
    for (int j=0;j<(N105+31)/32;j++){
        int r = lane + 32*j;
        if (r >= NSUP && r < N100){
            float best = p[j][0]; int bi = 0;
            #pragma unroll
            for (int k=1;k<WAYS;k++){ if (p[j][k] > best){ best = p[j][k]; bi = k; } }
            cnt += (bi == yq[b*NQ + (r-NSUP)]) ? 1 : 0;
        }
    }
    #pragma unroll
    for (int o=16;o;o>>=1) cnt += __shfl_xor_sync(0xffffffffu, cnt, o);
    if (lane==0) out[b] = (float)cnt / 75.0f;
}

extern "C" void kernel_launch(void* const* d_in, const int* in_sizes, int n_in,
                              void* d_out, int out_size){
    const float* xs = (const float*)d_in[0];
    const float* xq = (const float*)d_in[1];
    const int*   ys = (const int*)d_in[2];
    const int*   yq = (const int*)d_in[3];
    float* out = (float*)d_out;
    (void)in_sizes; (void)n_in; (void)out_size;

    k_zero<<<1,256>>>();                                   // 0
    k_front<<<RUNS,256>>>(xs, xq);                         // 1: proto + dist(e0) + sinkA75 s0
    k_mid<<<RUNS,256>>>(xs, xq, ys, 0, 1, 0);              // 2: sinkB75 s0 + upd + dist(e1) + sinkA75 s1
    k_mid<<<RUNS,256>>>(xs, xq, ys, 1, 2, 0);              // 3: sinkB75 s1 + upd + dist(e2) + sinkA75 s2
    k_mid<<<RUNS,256>>>(xs, xq, ys, 2, 0, 1);              // 4: sinkB75 s2 + FULL update
    k_gram0<<<RUNS,256>>>(xs, xq);                         // 5
    k_solve<<<RUNS,256>>>(xs, xq, ys);                     // 6: solve + sinkA105 s3
    k_final<<<RUNS/4,128>>>(ys, yq, out);                  // 7: sinkB105 s3 + acc
}